// round 7
// baseline (speedup 1.0000x reference)
#include <cuda_runtime.h>
#include <cuda_bf16.h>
#include <cstddef>
#include <cstdint>

#define HD   512
#define VOC  32000
#define TT1  128
#define TT2  64
#define NB   32
#define H3   1536
#define BHD  (NB*HD)
#define YSZ  ((size_t)TT2*NB*VOC)
#define HF_OFF YSZ
#define LS_OFF (YSZ + (size_t)2*BHD)

typedef unsigned int uint_t;

// ---------------- scratch (device globals; no runtime alloc) ----------------
__device__ float g_X  [TT2*NB*HD];
__device__ float g_q  [TT2*NB*HD];
__device__ float g_ep [TT1*NB*HD];
__device__ float g_sc [TT2*TT1*NB];
__device__ float g_av [TT2*NB*HD];
__device__ float g_gi0[TT2*NB*H3];
__device__ float g_ys [TT2*NB*HD];
__device__ float g_h0c[2*BHD];
__device__ float g_h1c[2*BHD];

// K-concat bf16 operands (A' = [hi|lo|hi], B' = [hi|hi|lo])
__device__ __nv_bfloat16 c_encc [(size_t)TT1*NB * 1536];
__device__ __nv_bfloat16 c_Wxc  [512  * 1536];
__device__ __nv_bfloat16 c_Wec  [512  * 1536];
__device__ __nv_bfloat16 c_Xc   [(size_t)TT2*NB * 1536];
__device__ __nv_bfloat16 c_Xavc [(size_t)TT2*NB * 3072];
__device__ __nv_bfloat16 c_Wih0c[(size_t)H3 * 3072];
__device__ __nv_bfloat16 c_oWc  [(size_t)VOC * 1536];
__device__ __nv_bfloat16 c_ysc  [(size_t)TT2*NB * 1536];

// grid barrier state
__device__ unsigned g_bgen = 0;
__device__ unsigned g_bcnt = 0;

__device__ __forceinline__ int CH(int b, int k){ return ((k>>2)<<7) + (b<<2) + (k&3); }

__device__ __forceinline__ float fast_tanh(float x){
    float e = __expf(2.f*x);
    return 1.f - __fdividef(2.f, e + 1.f);
}
__device__ __forceinline__ float fast_sig(float x){
    return __fdividef(1.f, 1.f + __expf(-x));
}

// ---------------- embed + state init ----------------
__global__ __launch_bounds__(256) void k_embed(const int* __restrict__ tok,
                                               const float* __restrict__ emb,
                                               const float* __restrict__ state)
{
    int i = blockIdx.x*256 + threadIdx.x;
    if (i < TT2*NB*HD){
        int row = i >> 9;
        int h   = i & (HD-1);
        g_X[i] = emb[(size_t)tok[row]*HD + h];
    }
    if (i < 2*BHD){
        int l = (i >= BHD);
        int r = i & (BHD-1);
        int b = r >> 9, h = r & (HD-1);
        float v = state[i];
        if (l == 0) g_h0c[CH(b,h)] = v;
        else        g_h1c[CH(b,h)] = v;
    }
}

// ---------------- fp32 -> K-concat bf16 split ----------------
// mode 0 (A side): [hi | lo | hi] ; mode 1 (B side): [hi | hi | lo]
__global__ void k_cat2(const float* __restrict__ src, int src_ld,
                       __nv_bfloat16* __restrict__ dst, int dst_ld,
                       int off, int span, int mode)
{
    int row = blockIdx.x;
    int k   = threadIdx.x * 4;
    float4 v = *reinterpret_cast<const float4*>(src + (size_t)row*src_ld + k);
    float xs[4] = {v.x, v.y, v.z, v.w};
    unsigned short h[4], l[4];
    #pragma unroll
    for (int j=0;j<4;j++){
        __nv_bfloat16 hb = __float2bfloat16(xs[j]);
        h[j] = __bfloat16_as_ushort(hb);
        l[j] = __bfloat16_as_ushort(__float2bfloat16(xs[j] - __bfloat162float(hb)));
    }
    uint2 hv = make_uint2(((uint_t)h[1]<<16)|h[0], ((uint_t)h[3]<<16)|h[2]);
    uint2 lv = make_uint2(((uint_t)l[1]<<16)|l[0], ((uint_t)l[3]<<16)|l[2]);
    __nv_bfloat16* b = dst + (size_t)row*dst_ld + off + k;
    *reinterpret_cast<uint2*>(b)          = hv;
    *reinterpret_cast<uint2*>(b +   span) = (mode == 0) ? lv : hv;
    *reinterpret_cast<uint2*>(b + 2*span) = (mode == 0) ? hv : lv;
}

// ---------------- bf16 GEMM: C[M,N] = A(M,K)*B(N,K)^T (+bias) ----------------
// 128x128 block tile, 8 warps (4M x 2N) of 32x64, BK=32,
// 3-stage cp.async ring, ONE __syncthreads per chunk, ldmatrix fragments.
__device__ __forceinline__ uint32_t s2u(const void* p){
    uint32_t a;
    asm("{ .reg .u64 t; cvta.to.shared.u64 t, %1; cvt.u32.u64 %0, t; }" : "=r"(a) : "l"(p));
    return a;
}
__device__ __forceinline__ void cpa16(uint32_t s, const void* g){
    asm volatile("cp.async.cg.shared.global [%0], [%1], 16;" :: "r"(s), "l"(g));
}
__device__ __forceinline__ void ldm4(uint32_t addr, uint32_t& r0, uint32_t& r1,
                                     uint32_t& r2, uint32_t& r3){
    asm volatile("ldmatrix.sync.aligned.m8n8.x4.shared.b16 {%0,%1,%2,%3}, [%4];"
        : "=r"(r0),"=r"(r1),"=r"(r2),"=r"(r3) : "r"(addr));
}
__device__ __forceinline__ void mma16(float* d, const uint32_t* a, uint32_t b0, uint32_t b1){
    asm volatile("mma.sync.aligned.m16n8k16.row.col.f32.bf16.bf16.f32 "
        "{%0,%1,%2,%3}, {%4,%5,%6,%7}, {%8,%9}, {%0,%1,%2,%3};\n"
        : "+f"(d[0]), "+f"(d[1]), "+f"(d[2]), "+f"(d[3])
        : "r"(a[0]), "r"(a[1]), "r"(a[2]), "r"(a[3]), "r"(b0), "r"(b1));
}

#define GROW 40   // padded smem row (bf16): 20-word stride -> conflict-free ldmatrix

__global__ __launch_bounds__(256, 2) void k_gemm(
    const __nv_bfloat16* __restrict__ A,
    const __nv_bfloat16* __restrict__ B,
    const float* __restrict__ bias,
    float* __restrict__ C, int N, int K)
{
    __shared__ __align__(16) __nv_bfloat16 sA[3][128*GROW];
    __shared__ __align__(16) __nv_bfloat16 sB[3][128*GROW];
    const int tid = threadIdx.x, lane = tid & 31, warp = tid >> 5;
    const int m0 = blockIdx.x * 128;
    const int n0 = blockIdx.y * 128;
    const int wm = (warp & 3) * 32;
    const int wn = (warp >> 2) * 64;

    const int frow = (lane & 7) + ((lane >> 3) & 1) * 8;
    const int fch  = (lane >> 4);

    const uint32_t sAu[3] = { s2u(&sA[0][0]), s2u(&sA[1][0]), s2u(&sA[2][0]) };
    const uint32_t sBu[3] = { s2u(&sB[0][0]), s2u(&sB[1][0]), s2u(&sB[2][0]) };

    const int lrow0 = tid >> 1;
    const int lch0  = (tid & 1) * 2;

    const int nch = K >> 5;
    float acc[2][8][4];
    #pragma unroll
    for (int i=0;i<2;i++)
        #pragma unroll
        for (int j=0;j<8;j++){ acc[i][j][0]=0.f; acc[i][j][1]=0.f; acc[i][j][2]=0.f; acc[i][j][3]=0.f; }

    auto load_stage = [&](int c){
        int s = c % 3;
        const __nv_bfloat16* ga = A + (size_t)(m0 + lrow0)*K + c*32 + lch0*8;
        const __nv_bfloat16* gb = B + (size_t)(n0 + lrow0)*K + c*32 + lch0*8;
        uint32_t da = sAu[s] + (lrow0*GROW + lch0*8)*2;
        uint32_t db = sBu[s] + (lrow0*GROW + lch0*8)*2;
        cpa16(da,      ga);
        cpa16(da + 16, ga + 8);
        cpa16(db,      gb);
        cpa16(db + 16, gb + 8);
        asm volatile("cp.async.commit_group;" ::: "memory");
    };

    load_stage(0);
    if (nch > 1) load_stage(1);

    for (int c = 0; c < nch; c++){
        if (c + 1 < nch) asm volatile("cp.async.wait_group 1;" ::: "memory");
        else             asm volatile("cp.async.wait_group 0;" ::: "memory");
        __syncthreads();
        // safe: buffer (c+2)%3 was last read by compute(c-1), finished before this barrier
        if (c + 2 < nch) load_stage(c + 2);
        const int s = c % 3;
        #pragma unroll
        for (int k16 = 0; k16 < 2; k16++){
            const int chb = k16*2 + fch;
            uint32_t a[2][4];
            #pragma unroll
            for (int mi=0; mi<2; mi++)
                ldm4(sAu[s] + ((wm + mi*16 + frow)*GROW + chb*8)*2,
                     a[mi][0], a[mi][1], a[mi][2], a[mi][3]);
            uint32_t b[4][4];
            #pragma unroll
            for (int nt2=0; nt2<4; nt2++)
                ldm4(sBu[s] + ((wn + nt2*16 + frow)*GROW + chb*8)*2,
                     b[nt2][0], b[nt2][1], b[nt2][2], b[nt2][3]);
            #pragma unroll
            for (int mi=0; mi<2; mi++)
                #pragma unroll
                for (int nt2=0; nt2<4; nt2++){
                    mma16(acc[mi][nt2*2+0], a[mi], b[nt2][0], b[nt2][2]);
                    mma16(acc[mi][nt2*2+1], a[mi], b[nt2][1], b[nt2][3]);
                }
        }
    }

    // epilogue
    #pragma unroll
    for (int mi=0; mi<2; mi++){
        #pragma unroll
        for (int nt=0; nt<8; nt++){
            int row = m0 + wm + mi*16 + (lane >> 2);
            int col = n0 + wn + nt*8 + (lane & 3)*2;
            float b0 = 0.f, b1 = 0.f;
            if (bias){ b0 = bias[col]; b1 = bias[col+1]; }
            float2 v0 = make_float2(acc[mi][nt][0]+b0, acc[mi][nt][1]+b1);
            float2 v1 = make_float2(acc[mi][nt][2]+b0, acc[mi][nt][3]+b1);
            *reinterpret_cast<float2*>(C + (size_t)row*N + col)     = v0;
            *reinterpret_cast<float2*>(C + (size_t)(row+8)*N + col) = v1;
        }
    }
}

// ---------------- attention logits + softmax ----------------
__global__ __launch_bounds__(256) void k_att_scores(const float* __restrict__ va,
                                                    float* __restrict__ dout)
{
    __shared__ float q8[8*HD];
    __shared__ float vsm[HD];
    __shared__ float esm[8*TT1];
    const int b   = blockIdx.y;
    const int t2b = blockIdx.x * 8;
    const int tid = threadIdx.x, lane = tid & 31, w = tid >> 5;

    for (int i = tid; i < 8*HD; i += 256){
        int t2i = i >> 9, h = i & (HD-1);
        q8[i] = g_q[((size_t)(t2b + t2i)*NB + b)*HD + h];
    }
    for (int i = tid; i < HD; i += 256) vsm[i] = va[i];
    __syncthreads();

    for (int t1 = w; t1 < TT1; t1 += 8){
        const float* ep = g_ep + ((size_t)t1*NB + b)*HD;
        float accv[8];
        #pragma unroll
        for (int i=0;i<8;i++) accv[i] = 0.f;
        for (int h = lane; h < HD; h += 32){
            float e  = ep[h];
            float vv = vsm[h];
            #pragma unroll
            for (int i=0;i<8;i++) accv[i] += vv * fast_tanh(q8[i*HD + h] + e);
        }
        #pragma unroll
        for (int i=0;i<8;i++){
            float s = accv[i];
            #pragma unroll
            for (int o=16;o;o>>=1) s += __shfl_xor_sync(0xffffffffu, s, o);
            if (lane == 0) esm[i*TT1 + t1] = s;
        }
    }
    __syncthreads();

    {
        float v[4];
        #pragma unroll
        for (int i=0;i<4;i++) v[i] = esm[w*TT1 + lane + 32*i];
        float m = fmaxf(fmaxf(v[0],v[1]), fmaxf(v[2],v[3]));
        #pragma unroll
        for (int o=16;o;o>>=1) m = fmaxf(m, __shfl_xor_sync(0xffffffffu, m, o));
        float s = 0.f;
        #pragma unroll
        for (int i=0;i<4;i++){ v[i] = __expf(v[i]-m); s += v[i]; }
        #pragma unroll
        for (int o=16;o;o>>=1) s += __shfl_xor_sync(0xffffffffu, s, o);
        float inv = __fdividef(1.f, s);
        int t2 = t2b + w;
        #pragma unroll
        for (int i=0;i<4;i++){
            int t1 = lane + 32*i;
            float sc = v[i]*inv;
            g_sc[((size_t)t2*TT1 + t1)*NB + b] = sc;
            if (t2 == TT2-1) dout[LS_OFF + (size_t)t1*NB + b] = sc;
        }
    }
}

// ---------------- attention values ----------------
__global__ __launch_bounds__(256) void k_attv(const float* __restrict__ enc)
{
    __shared__ float sst[TT1*32];
    const int b   = blockIdx.x;
    const int t2o = blockIdx.y * 32;
    const int h   = blockIdx.z * 256 + threadIdx.x;
    for (int i = threadIdx.x; i < 32*TT1; i += 256){
        int t1 = i >> 5, i2 = i & 31;
        sst[t1*32 + i2] = g_sc[((size_t)(t2o + i2)*TT1 + t1)*NB + b];
    }
    __syncthreads();
    float acc[32];
    #pragma unroll
    for (int i=0;i<32;i++) acc[i] = 0.f;
    for (int t1 = 0; t1 < TT1; t1++){
        float ev = enc[((size_t)t1*NB + b)*HD + h];
        #pragma unroll
        for (int i=0;i<32;i++) acc[i] += ev * sst[t1*32 + i];
    }
    #pragma unroll
    for (int i=0;i<32;i++)
        g_av[((size_t)(t2o+i)*NB + b)*HD + h] = acc[i];
}

// ---------------- persistent recurrence ----------------
__device__ __forceinline__ void dot3(const float* __restrict__ W, int j,
                                     const float* __restrict__ hch, int b,
                                     float& s0, float& s1, float& s2)
{
    const float* w0 = W + (size_t) j        *HD;
    const float* w1 = W + (size_t)(j+ 512)  *HD;
    const float* w2 = W + (size_t)(j+1024)  *HD;
    float a0=0.f, a1=0.f, a2=0.f;
    #pragma unroll 4
    for (int k = 0; k < HD; k += 4){
        float4 hv = __ldcg(reinterpret_cast<const float4*>(hch + ((k>>2)<<7) + (b<<2)));
        float4 x = *reinterpret_cast<const float4*>(w0 + k);
        float4 y = *reinterpret_cast<const float4*>(w1 + k);
        float4 z = *reinterpret_cast<const float4*>(w2 + k);
        a0 += x.x*hv.x + x.y*hv.y + x.z*hv.z + x.w*hv.w;
        a1 += y.x*hv.x + y.y*hv.y + y.z*hv.z + y.w*hv.w;
        a2 += z.x*hv.x + z.y*hv.y + z.z*hv.z + z.w*hv.w;
    }
    s0 = a0; s1 = a1; s2 = a2;
}

#define NBLK 192

__global__ __launch_bounds__(256, 2) void k_rec(
    const float* __restrict__ W_hh0, const float* __restrict__ b_hh0,
    const float* __restrict__ W_ih1, const float* __restrict__ b_ih1,
    const float* __restrict__ W_hh1, const float* __restrict__ b_hh1)
{
    const int blk  = blockIdx.x;
    const int warp = threadIdx.x >> 5;
    const int b    = threadIdx.x & 31;
    __shared__ float sm[8][3][32];
    __shared__ unsigned s_gen;
    if (threadIdx.x == 0) s_gen = atomicAdd(&g_bgen, 0u);
    __syncthreads();
    const unsigned G0 = s_gen;

    for (int t = 0; t <= TT2; t++){
        if (blk < 64){
            if (t < TT2){
                const int j = blk*8 + warp;
                const int p = t & 1;
                const float* hch = g_h0c + p*BHD;
                float s0, s1, s2;
                dot3(W_hh0, j, hch, b, s0, s1, s2);
                const float* gi = g_gi0 + ((size_t)t*NB + b)*H3;
                float r = fast_sig (gi[j      ] + s0 + b_hh0[j      ]);
                float z = fast_sig (gi[j+ 512] + s1 + b_hh0[j+ 512]);
                float n = fast_tanh(gi[j+1024] + r*(s2 + b_hh0[j+1024]));
                float hold = __ldcg(&hch[CH(b,j)]);
                __stcg(&g_h0c[(1-p)*BHD + CH(b,j)], (1.f-z)*n + z*hold);
            }
        } else {
            if (t >= 1){
                const int s    = t - 1;
                const int blk2 = blk - 64;
                const int j    = blk2*4 + (warp >> 1);
                const int mat  = warp & 1;
                const int p1   = s & 1;
                const float* hin = (mat == 0) ? (g_h0c + ((s+1)&1)*BHD)
                                              : (g_h1c + p1*BHD);
                const float* W   = (mat == 0) ? W_ih1 : W_hh1;
                float s0, s1, s2;
                dot3(W, j, hin, b, s0, s1, s2);
                sm[warp][0][b] = s0; sm[warp][1][b] = s1; sm[warp][2][b] = s2;
                __syncthreads();
                if (mat == 0){
                    float xr = s0 + b_ih1[j      ];
                    float xz = s1 + b_ih1[j+ 512];
                    float xn = s2 + b_ih1[j+1024];
                    float hr = sm[warp+1][0][b] + b_hh1[j      ];
                    float hz = sm[warp+1][1][b] + b_hh1[j+ 512];
                    float hn = sm[warp+1][2][b] + b_hh1[j+1024];
                    float r = fast_sig(xr + hr);
                    float z = fast_sig(xz + hz);
                    float n = fast_tanh(xn + r*hn);
                    float h1old = __ldcg(&g_h1c[p1*BHD + CH(b,j)]);
                    float hnew = (1.f-z)*n + z*h1old;
                    __stcg(&g_h1c[((s+1)&1)*BHD + CH(b,j)], hnew);
                    g_ys[((size_t)s*NB + b)*HD + j] = hnew;
                }
            }
        }
        if (t == TT2) break;
        __syncthreads();
        if (threadIdx.x == 0){
            __threadfence();
            unsigned a = atomicAdd(&g_bcnt, 1u);
            if (a == NBLK-1u){
                atomicExch(&g_bcnt, 0u);
                __threadfence();
                atomicAdd(&g_bgen, 1u);
            } else {
                unsigned target = G0 + (unsigned)t + 1u;
                while ((int)(*(volatile unsigned*)&g_bgen - target) < 0) __nanosleep(64);
            }
            __threadfence();
        }
        __syncthreads();
    }
}

// ---------------- final state copy ----------------
__global__ __launch_bounds__(256) void k_fin(float* __restrict__ dout)
{
    int i = blockIdx.x*256 + threadIdx.x;
    if (i >= 2*BHD) return;
    int l = (i >= BHD);
    int r = i & (BHD-1);
    int b = r >> 9, h = r & (HD-1);
    float v = l ? g_h1c[CH(b,h)] : g_h0c[CH(b,h)];
    dout[HF_OFF + i] = v;
}

extern "C" void kernel_launch(void* const* d_in, const int* in_sizes, int n_in,
                              void* d_out, int out_size)
{
    const int*   tok   = (const int*)  d_in[0];
    const float* state = (const float*)d_in[1];
    const float* enc   = (const float*)d_in[2];
    const float* emb   = (const float*)d_in[3];
    const float* wa_W  = (const float*)d_in[4];
    const float* wa_b  = (const float*)d_in[5];
    const float* va_W  = (const float*)d_in[6];
    const float* W_ih0 = (const float*)d_in[7];
    const float* W_hh0 = (const float*)d_in[8];
    const float* b_ih0 = (const float*)d_in[9];
    const float* b_hh0 = (const float*)d_in[10];
    const float* W_ih1 = (const float*)d_in[11];
    const float* W_hh1 = (const float*)d_in[12];
    const float* b_ih1 = (const float*)d_in[13];
    const float* b_hh1 = (const float*)d_in[14];
    const float* out_W = (const float*)d_in[15];
    const float* out_b = (const float*)d_in[16];
    float* dout = (float*)d_out;

    float *pX, *pep, *pq, *pav, *pgi0, *pys;
    __nv_bfloat16 *pencc, *pWxc, *pWec, *pXc, *pXavc, *pWih0c, *poWc, *pysc;
    cudaGetSymbolAddress((void**)&pX,     g_X);
    cudaGetSymbolAddress((void**)&pep,    g_ep);
    cudaGetSymbolAddress((void**)&pq,     g_q);
    cudaGetSymbolAddress((void**)&pav,    g_av);
    cudaGetSymbolAddress((void**)&pgi0,   g_gi0);
    cudaGetSymbolAddress((void**)&pys,    g_ys);
    cudaGetSymbolAddress((void**)&pencc,  c_encc);
    cudaGetSymbolAddress((void**)&pWxc,   c_Wxc);
    cudaGetSymbolAddress((void**)&pWec,   c_Wec);
    cudaGetSymbolAddress((void**)&pXc,    c_Xc);
    cudaGetSymbolAddress((void**)&pXavc,  c_Xavc);
    cudaGetSymbolAddress((void**)&pWih0c, c_Wih0c);
    cudaGetSymbolAddress((void**)&poWc,   c_oWc);
    cudaGetSymbolAddress((void**)&pysc,   c_ysc);

    // launch order arranged so the 6th launch is a k_gemm (for ncu -s 5 -c 1)
    // 1. embed + state init
    k_embed<<<(TT2*NB*HD + 255)/256, 256>>>(tok, emb, state);
    // 2-5. conversions needed for enc_proj + q
    k_cat2<<<TT1*NB, 128>>>(enc,        HD,   pencc,  1536, 0, 512, 0);
    k_cat2<<<512,    128>>>(wa_W + HD,  2*HD, pWec,   1536, 0, 512, 1);
    k_cat2<<<512,    128>>>(wa_W,       2*HD, pWxc,   1536, 0, 512, 1);
    k_cat2<<<TT2*NB, 128>>>(pX,         HD,   pXc,    1536, 0, 512, 0);
    // 6. enc_proj = enc @ We^T + wa_b    (M=4096, N=512, K'=1536)  << profiled
    k_gemm<<<dim3((TT1*NB)/128, HD/128), 256>>>(pencc, pWec, wa_b, pep, HD, 1536);
    // 7. q = X @ Wx^T
    k_gemm<<<dim3((TT2*NB)/128, HD/128), 256>>>(pXc, pWxc, nullptr, pq, HD, 1536);
    // 8-10. remaining conversions
    k_cat2<<<H3,     256>>>(W_ih0,      2*HD, pWih0c, 3072, 0, 1024, 1);
    k_cat2<<<VOC,    128>>>(out_W,      HD,   poWc,   1536, 0, 512, 1);
    k_cat2<<<TT2*NB, 128>>>(pX,         HD,   pXavc,  3072, 0, 1024, 0);
    // 11. attention scores + softmax (writes last_score)
    k_att_scores<<<dim3(TT2/8, NB), 256>>>(va_W, dout);
    // 12. attention values
    k_attv<<<dim3(NB, TT2/32, HD/256), 256>>>(enc);
    // 13. att_v into c_Xavc columns [512:1024) of each span
    k_cat2<<<TT2*NB, 128>>>(pav, HD, pXavc, 3072, 512, 1024, 0);
    // 14. gi0 = [X, att_v] @ W_ih0^T + b_ih0   (M=2048, N=1536, K'=3072)
    k_gemm<<<dim3((TT2*NB)/128, H3/128), 256>>>(pXavc, pWih0c, b_ih0, pgi0, H3, 3072);
    // 15. persistent recurrence
    k_rec<<<NBLK, 256>>>(W_hh0, b_hh0, W_ih1, b_ih1, W_hh1, b_hh1);
    // 16-17. y = ys @ out_W^T + out_b    (M=2048, N=32000, K'=1536)
    k_cat2<<<TT2*NB, 128>>>(pys, HD, pysc, 1536, 0, 512, 0);
    k_gemm<<<dim3((TT2*NB)/128, VOC/128), 256>>>(pysc, poWc, out_b, dout, VOC, 1536);
    // 18. final hidden states
    k_fin<<<(2*BHD + 255)/256, 256>>>(dout);
    (void)in_sizes; (void)n_in; (void)out_size;
}

// round 8
// speedup vs baseline: 1.1836x; 1.1836x over previous
#include <cuda_runtime.h>
#include <cuda_fp16.h>
#include <cstddef>
#include <cstdint>

#define HD   512
#define VOC  32000
#define TT1  128
#define TT2  64
#define NB   32
#define H3   1536
#define BHD  (NB*HD)
#define YSZ  ((size_t)TT2*NB*VOC)
#define HF_OFF YSZ
#define LS_OFF (YSZ + (size_t)2*BHD)

typedef unsigned int uint_t;

// ---------------- scratch (device globals; no runtime alloc) ----------------
__device__ float g_X  [TT2*NB*HD];
__device__ float g_q  [TT2*NB*HD];
__device__ float g_ep [TT1*NB*HD];
__device__ float g_sc [TT2*TT1*NB];
__device__ float g_av [TT2*NB*HD];
__device__ float g_gi0[TT2*NB*H3];
__device__ float g_ys [TT2*NB*HD];
__device__ float g_h0c[2*BHD];
__device__ float g_h1c[2*BHD];

// fp16 operands
__device__ __align__(16) __half h_ench [(size_t)TT1*NB * 1024];  // A2: [hi|lo]
__device__ __align__(16) __half h_Wxh  [512 * 1024];             // B2: [hi|hi]
__device__ __align__(16) __half h_Weh  [512 * 1024];             // B2
__device__ __align__(16) __half h_Xh   [(size_t)TT2*NB * 1024];  // A2
__device__ __align__(16) __half h_Xavh [(size_t)TT2*NB * 2048];  // A2 of [X|av]
__device__ __align__(16) __half h_Wih0h[(size_t)H3 * 2048];      // B2
__device__ __align__(16) __half h_oWh  [(size_t)VOC * 512];      // 1-term
__device__ __align__(16) __half h_ysh  [(size_t)TT2*NB * 512];   // 1-term

// grid barrier state
__device__ unsigned g_bgen = 0;
__device__ unsigned g_bcnt = 0;

__device__ __forceinline__ int CH(int b, int k){ return ((k>>2)<<7) + (b<<2) + (k&3); }

__device__ __forceinline__ float fast_tanh(float x){
    float e = __expf(2.f*x);
    return 1.f - __fdividef(2.f, e + 1.f);
}
__device__ __forceinline__ float fast_sig(float x){
    return __fdividef(1.f, 1.f + __expf(-x));
}

// ---------------- embed + state init ----------------
__global__ __launch_bounds__(256) void k_embed(const int* __restrict__ tok,
                                               const float* __restrict__ emb,
                                               const float* __restrict__ state)
{
    int i = blockIdx.x*256 + threadIdx.x;
    if (i < TT2*NB*HD){
        int row = i >> 9;
        int h   = i & (HD-1);
        g_X[i] = emb[(size_t)tok[row]*HD + h];
    }
    if (i < 2*BHD){
        int l = (i >= BHD);
        int r = i & (BHD-1);
        int b = r >> 9, h = r & (HD-1);
        float v = state[i];
        if (l == 0) g_h0c[CH(b,h)] = v;
        else        g_h1c[CH(b,h)] = v;
    }
}

// ---------------- fp32 -> fp16 split conversion ----------------
// mode 0 (A2): hi at off0, lo at off1 ; mode 1 (B2): hi at off0 and off1 ;
// mode 2: hi at off0 only.
__device__ __forceinline__ uint_t packh(__half a, __half b){
    return ((uint_t)__half_as_ushort(b) << 16) | (uint_t)__half_as_ushort(a);
}
__global__ void k_cath(const float* __restrict__ src, int src_ld, int Ksrc,
                       __half* __restrict__ dst, int dst_ld,
                       int off0, int off1, int mode)
{
    int row = blockIdx.x;
    for (int k = threadIdx.x*4; k < Ksrc; k += blockDim.x*4){
        float4 v = *reinterpret_cast<const float4*>(src + (size_t)row*src_ld + k);
        __half h0 = __float2half_rn(v.x), h1 = __float2half_rn(v.y);
        __half h2 = __float2half_rn(v.z), h3 = __float2half_rn(v.w);
        uint2 hv = make_uint2(packh(h0,h1), packh(h2,h3));
        *reinterpret_cast<uint2*>(dst + (size_t)row*dst_ld + off0 + k) = hv;
        if (mode == 0){
            __half l0 = __float2half_rn(v.x - __half2float(h0));
            __half l1 = __float2half_rn(v.y - __half2float(h1));
            __half l2 = __float2half_rn(v.z - __half2float(h2));
            __half l3 = __float2half_rn(v.w - __half2float(h3));
            uint2 lv = make_uint2(packh(l0,l1), packh(l2,l3));
            *reinterpret_cast<uint2*>(dst + (size_t)row*dst_ld + off1 + k) = lv;
        } else if (mode == 1){
            *reinterpret_cast<uint2*>(dst + (size_t)row*dst_ld + off1 + k) = hv;
        }
    }
}

// ---------------- fp16 GEMM: C[M,N] = A(M,K)*B(N,K)^T (+bias) ----------------
// 128x128 block tile, 8 warps (2M x 4N) of 64x32. Scalar-LDS fragments
// (R4-proven layout). At legacy-HMMA rt ceiling; LDS has large headroom.
__device__ __forceinline__ void mma16f(float* d, const uint_t* a, uint_t b0, uint_t b1){
    asm volatile("mma.sync.aligned.m16n8k16.row.col.f32.f16.f16.f32 "
        "{%0,%1,%2,%3}, {%4,%5,%6,%7}, {%8,%9}, {%0,%1,%2,%3};\n"
        : "+f"(d[0]), "+f"(d[1]), "+f"(d[2]), "+f"(d[3])
        : "r"(a[0]), "r"(a[1]), "r"(a[2]), "r"(a[3]), "r"(b0), "r"(b1));
}
#define SKH 136

__global__ __launch_bounds__(256, 2) void k_gemmh(
    const uint_t* __restrict__ A, int lda,   // lda in uint (fp16x2) units = K/2
    const uint_t* __restrict__ B, int ldb,
    const float* __restrict__ bias,
    float* __restrict__ C, int ldc, int K)
{
    __shared__ uint_t sA[16*SKH], sB[16*SKH];
    const int m0 = blockIdx.y * 128;
    const int n0 = blockIdx.x * 128;
    const int tid = threadIdx.x, lane = tid & 31, warp = tid >> 5;
    const int wm = (warp & 1) * 64;
    const int wn = (warp >> 1) * 32;
    const int g  = lane >> 2, tg = lane & 3;

    float acc[4][4][4];
    #pragma unroll
    for (int i=0;i<4;i++)
        #pragma unroll
        for (int j=0;j<4;j++){ acc[i][j][0]=0.f; acc[i][j][1]=0.f; acc[i][j][2]=0.f; acc[i][j][3]=0.f; }

    for (int k0 = 0; k0 < K; k0 += 32){
        const int khu = k0 >> 1;          // uint col base
        #pragma unroll
        for (int i=0;i<2;i++){
            int idx = i*256 + tid;        // 0..511
            int row = idx >> 2;           // 0..127
            int p   = (idx & 3) * 4;      // uint index within 16-uint row chunk
            uint4 va = *reinterpret_cast<const uint4*>(A + (size_t)(m0+row)*lda + khu + p);
            sA[(p+0)*SKH + row] = va.x;  sA[(p+1)*SKH + row] = va.y;
            sA[(p+2)*SKH + row] = va.z;  sA[(p+3)*SKH + row] = va.w;
            uint4 vb = *reinterpret_cast<const uint4*>(B + (size_t)(n0+row)*ldb + khu + p);
            sB[(p+0)*SKH + row] = vb.x;  sB[(p+1)*SKH + row] = vb.y;
            sB[(p+2)*SKH + row] = vb.z;  sB[(p+3)*SKH + row] = vb.w;
        }
        __syncthreads();
        #pragma unroll
        for (int h2=0; h2<2; h2++){
            const int kb2 = h2*8;
            #pragma unroll
            for (int mp=0; mp<2; mp++){
                uint_t ah[2][4];
                #pragma unroll
                for (int q=0;q<2;q++){
                    int rowb  = wm + (mp*2+q)*16 + g;
                    int base0 = (kb2+tg  )*SKH + rowb;
                    int base1 = (kb2+tg+4)*SKH + rowb;
                    ah[q][0]=sA[base0]; ah[q][1]=sA[base0+8];
                    ah[q][2]=sA[base1]; ah[q][3]=sA[base1+8];
                }
                #pragma unroll
                for (int ns=0; ns<4; ns++){
                    int col = wn + ns*8 + g;
                    uint_t b0 = sB[(kb2+tg  )*SKH + col];
                    uint_t b1 = sB[(kb2+tg+4)*SKH + col];
                    #pragma unroll
                    for (int q=0;q<2;q++)
                        mma16f(acc[mp*2+q][ns], ah[q], b0, b1);
                }
            }
        }
        __syncthreads();
    }
    #pragma unroll
    for (int ms=0; ms<4; ms++){
        #pragma unroll
        for (int ns=0; ns<4; ns++){
            int r0  = m0 + wm + ms*16 + g;
            int col = n0 + wn + ns*8 + tg*2;
            float b0v = 0.f, b1v = 0.f;
            if (bias){ b0v = bias[col]; b1v = bias[col+1]; }
            float* p0 = C + (size_t)r0*ldc + col;
            float* p1 = C + (size_t)(r0+8)*ldc + col;
            p0[0] = acc[ms][ns][0]+b0v;  p0[1] = acc[ms][ns][1]+b1v;
            p1[0] = acc[ms][ns][2]+b0v;  p1[1] = acc[ms][ns][3]+b1v;
        }
    }
}

// ---------------- attention logits + softmax ----------------
__global__ __launch_bounds__(256) void k_att_scores(const float* __restrict__ va,
                                                    float* __restrict__ dout)
{
    __shared__ float q8[8*HD];
    __shared__ float vsm[HD];
    __shared__ float esm[8*TT1];
    const int b   = blockIdx.y;
    const int t2b = blockIdx.x * 8;
    const int tid = threadIdx.x, lane = tid & 31, w = tid >> 5;

    for (int i = tid; i < 8*HD; i += 256){
        int t2i = i >> 9, h = i & (HD-1);
        q8[i] = g_q[((size_t)(t2b + t2i)*NB + b)*HD + h];
    }
    for (int i = tid; i < HD; i += 256) vsm[i] = va[i];
    __syncthreads();

    for (int t1 = w; t1 < TT1; t1 += 8){
        const float* ep = g_ep + ((size_t)t1*NB + b)*HD;
        float accv[8];
        #pragma unroll
        for (int i=0;i<8;i++) accv[i] = 0.f;
        for (int h = lane; h < HD; h += 32){
            float e  = ep[h];
            float vv = vsm[h];
            #pragma unroll
            for (int i=0;i<8;i++) accv[i] += vv * fast_tanh(q8[i*HD + h] + e);
        }
        #pragma unroll
        for (int i=0;i<8;i++){
            float s = accv[i];
            #pragma unroll
            for (int o=16;o;o>>=1) s += __shfl_xor_sync(0xffffffffu, s, o);
            if (lane == 0) esm[i*TT1 + t1] = s;
        }
    }
    __syncthreads();

    {
        float v[4];
        #pragma unroll
        for (int i=0;i<4;i++) v[i] = esm[w*TT1 + lane + 32*i];
        float m = fmaxf(fmaxf(v[0],v[1]), fmaxf(v[2],v[3]));
        #pragma unroll
        for (int o=16;o;o>>=1) m = fmaxf(m, __shfl_xor_sync(0xffffffffu, m, o));
        float s = 0.f;
        #pragma unroll
        for (int i=0;i<4;i++){ v[i] = __expf(v[i]-m); s += v[i]; }
        #pragma unroll
        for (int o=16;o;o>>=1) s += __shfl_xor_sync(0xffffffffu, s, o);
        float inv = __fdividef(1.f, s);
        int t2 = t2b + w;
        #pragma unroll
        for (int i=0;i<4;i++){
            int t1 = lane + 32*i;
            float sc = v[i]*inv;
            g_sc[((size_t)t2*TT1 + t1)*NB + b] = sc;
            if (t2 == TT2-1) dout[LS_OFF + (size_t)t1*NB + b] = sc;
        }
    }
}

// ---------------- attention values ----------------
__global__ __launch_bounds__(256) void k_attv(const float* __restrict__ enc)
{
    __shared__ float sst[TT1*32];
    const int b   = blockIdx.x;
    const int t2o = blockIdx.y * 32;
    const int h   = blockIdx.z * 256 + threadIdx.x;
    for (int i = threadIdx.x; i < 32*TT1; i += 256){
        int t1 = i >> 5, i2 = i & 31;
        sst[t1*32 + i2] = g_sc[((size_t)(t2o + i2)*TT1 + t1)*NB + b];
    }
    __syncthreads();
    float acc[32];
    #pragma unroll
    for (int i=0;i<32;i++) acc[i] = 0.f;
    for (int t1 = 0; t1 < TT1; t1++){
        float ev = enc[((size_t)t1*NB + b)*HD + h];
        #pragma unroll
        for (int i=0;i<32;i++) acc[i] += ev * sst[t1*32 + i];
    }
    #pragma unroll
    for (int i=0;i<32;i++)
        g_av[((size_t)(t2o+i)*NB + b)*HD + h] = acc[i];
}

// ---------------- persistent recurrence ----------------
__device__ __forceinline__ void dot3(const float* __restrict__ W, int j,
                                     const float* __restrict__ hch, int b,
                                     float& s0, float& s1, float& s2)
{
    const float* w0 = W + (size_t) j        *HD;
    const float* w1 = W + (size_t)(j+ 512)  *HD;
    const float* w2 = W + (size_t)(j+1024)  *HD;
    float a0=0.f, a1=0.f, a2=0.f;
    #pragma unroll 4
    for (int k = 0; k < HD; k += 4){
        float4 hv = __ldcg(reinterpret_cast<const float4*>(hch + ((k>>2)<<7) + (b<<2)));
        float4 x = *reinterpret_cast<const float4*>(w0 + k);
        float4 y = *reinterpret_cast<const float4*>(w1 + k);
        float4 z = *reinterpret_cast<const float4*>(w2 + k);
        a0 += x.x*hv.x + x.y*hv.y + x.z*hv.z + x.w*hv.w;
        a1 += y.x*hv.x + y.y*hv.y + y.z*hv.z + y.w*hv.w;
        a2 += z.x*hv.x + z.y*hv.y + z.z*hv.z + z.w*hv.w;
    }
    s0 = a0; s1 = a1; s2 = a2;
}

#define NBLK 192

__global__ __launch_bounds__(256, 2) void k_rec(
    const float* __restrict__ W_hh0, const float* __restrict__ b_hh0,
    const float* __restrict__ W_ih1, const float* __restrict__ b_ih1,
    const float* __restrict__ W_hh1, const float* __restrict__ b_hh1)
{
    const int blk  = blockIdx.x;
    const int warp = threadIdx.x >> 5;
    const int b    = threadIdx.x & 31;
    __shared__ float sm[8][3][32];
    __shared__ unsigned s_gen;
    if (threadIdx.x == 0) s_gen = atomicAdd(&g_bgen, 0u);
    __syncthreads();
    const unsigned G0 = s_gen;

    for (int t = 0; t <= TT2; t++){
        if (blk < 64){
            if (t < TT2){
                const int j = blk*8 + warp;
                const int p = t & 1;
                const float* hch = g_h0c + p*BHD;
                float s0, s1, s2;
                dot3(W_hh0, j, hch, b, s0, s1, s2);
                const float* gi = g_gi0 + ((size_t)t*NB + b)*H3;
                float r = fast_sig (gi[j      ] + s0 + b_hh0[j      ]);
                float z = fast_sig (gi[j+ 512] + s1 + b_hh0[j+ 512]);
                float n = fast_tanh(gi[j+1024] + r*(s2 + b_hh0[j+1024]));
                float hold = __ldcg(&hch[CH(b,j)]);
                __stcg(&g_h0c[(1-p)*BHD + CH(b,j)], (1.f-z)*n + z*hold);
            }
        } else {
            if (t >= 1){
                const int s    = t - 1;
                const int blk2 = blk - 64;
                const int j    = blk2*4 + (warp >> 1);
                const int mat  = warp & 1;
                const int p1   = s & 1;
                const float* hin = (mat == 0) ? (g_h0c + ((s+1)&1)*BHD)
                                              : (g_h1c + p1*BHD);
                const float* W   = (mat == 0) ? W_ih1 : W_hh1;
                float s0, s1, s2;
                dot3(W, j, hin, b, s0, s1, s2);
                sm[warp][0][b] = s0; sm[warp][1][b] = s1; sm[warp][2][b] = s2;
                __syncthreads();
                if (mat == 0){
                    float xr = s0 + b_ih1[j      ];
                    float xz = s1 + b_ih1[j+ 512];
                    float xn = s2 + b_ih1[j+1024];
                    float hr = sm[warp+1][0][b] + b_hh1[j      ];
                    float hz = sm[warp+1][1][b] + b_hh1[j+ 512];
                    float hn = sm[warp+1][2][b] + b_hh1[j+1024];
                    float r = fast_sig(xr + hr);
                    float z = fast_sig(xz + hz);
                    float n = fast_tanh(xn + r*hn);
                    float h1old = __ldcg(&g_h1c[p1*BHD + CH(b,j)]);
                    float hnew = (1.f-z)*n + z*h1old;
                    __stcg(&g_h1c[((s+1)&1)*BHD + CH(b,j)], hnew);
                    g_ys[((size_t)s*NB + b)*HD + j] = hnew;
                }
            }
        }
        if (t == TT2) break;
        __syncthreads();
        if (threadIdx.x == 0){
            __threadfence();
            unsigned a = atomicAdd(&g_bcnt, 1u);
            if (a == NBLK-1u){
                atomicExch(&g_bcnt, 0u);
                __threadfence();
                atomicAdd(&g_bgen, 1u);
            } else {
                unsigned target = G0 + (unsigned)t + 1u;
                while ((int)(*(volatile unsigned*)&g_bgen - target) < 0) __nanosleep(64);
            }
            __threadfence();
        }
        __syncthreads();
    }
}

// ---------------- final state copy ----------------
__global__ __launch_bounds__(256) void k_fin(float* __restrict__ dout)
{
    int i = blockIdx.x*256 + threadIdx.x;
    if (i >= 2*BHD) return;
    int l = (i >= BHD);
    int r = i & (BHD-1);
    int b = r >> 9, h = r & (HD-1);
    float v = l ? g_h1c[CH(b,h)] : g_h0c[CH(b,h)];
    dout[HF_OFF + i] = v;
}

extern "C" void kernel_launch(void* const* d_in, const int* in_sizes, int n_in,
                              void* d_out, int out_size)
{
    const int*   tok   = (const int*)  d_in[0];
    const float* state = (const float*)d_in[1];
    const float* enc   = (const float*)d_in[2];
    const float* emb   = (const float*)d_in[3];
    const float* wa_W  = (const float*)d_in[4];
    const float* wa_b  = (const float*)d_in[5];
    const float* va_W  = (const float*)d_in[6];
    const float* W_ih0 = (const float*)d_in[7];
    const float* W_hh0 = (const float*)d_in[8];
    const float* b_ih0 = (const float*)d_in[9];
    const float* b_hh0 = (const float*)d_in[10];
    const float* W_ih1 = (const float*)d_in[11];
    const float* W_hh1 = (const float*)d_in[12];
    const float* b_ih1 = (const float*)d_in[13];
    const float* b_hh1 = (const float*)d_in[14];
    const float* out_W = (const float*)d_in[15];
    const float* out_b = (const float*)d_in[16];
    float* dout = (float*)d_out;

    float *pX, *pep, *pq, *pav, *pgi0, *pys;
    __half *pench, *pWxh, *pWeh, *pXh, *pXavh, *pWih0h, *poWh, *pysh;
    cudaGetSymbolAddress((void**)&pX,     g_X);
    cudaGetSymbolAddress((void**)&pep,    g_ep);
    cudaGetSymbolAddress((void**)&pq,     g_q);
    cudaGetSymbolAddress((void**)&pav,    g_av);
    cudaGetSymbolAddress((void**)&pgi0,   g_gi0);
    cudaGetSymbolAddress((void**)&pys,    g_ys);
    cudaGetSymbolAddress((void**)&pench,  h_ench);
    cudaGetSymbolAddress((void**)&pWxh,   h_Wxh);
    cudaGetSymbolAddress((void**)&pWeh,   h_Weh);
    cudaGetSymbolAddress((void**)&pXh,    h_Xh);
    cudaGetSymbolAddress((void**)&pXavh,  h_Xavh);
    cudaGetSymbolAddress((void**)&pWih0h, h_Wih0h);
    cudaGetSymbolAddress((void**)&poWh,   h_oWh);
    cudaGetSymbolAddress((void**)&pysh,   h_ysh);

    // 1. embed + state init
    k_embed<<<(TT2*NB*HD + 255)/256, 256>>>(tok, emb, state);

    // 2. conversions for enc_proj + q
    k_cath<<<TT1*NB, 128>>>(enc,        HD, HD, pench, 1024, 0, 512, 0);   // A2
    k_cath<<<512,    128>>>(wa_W + HD, 2*HD, HD, pWeh, 1024, 0, 512, 1);   // B2
    k_cath<<<512,    128>>>(wa_W,      2*HD, HD, pWxh, 1024, 0, 512, 1);   // B2
    k_cath<<<TT2*NB, 128>>>(pX,         HD, HD, pXh,  1024, 0, 512, 0);    // A2

    // 6th launch: GEMM (for ncu -s 5 -c 1)
    // enc_proj = enc @ We^T + wa_b   (M=4096, N=512, K'=1024)
    k_gemmh<<<dim3(HD/128, (TT1*NB)/128), 256>>>((const uint_t*)pench, 512,
        (const uint_t*)pWeh, 512, wa_b, pep, HD, 1024);
    // q = X @ Wx^T                   (M=2048, N=512, K'=1024)
    k_gemmh<<<dim3(HD/128, (TT2*NB)/128), 256>>>((const uint_t*)pXh, 512,
        (const uint_t*)pWxh, 512, nullptr, pq, HD, 1024);

    // remaining conversions
    k_cath<<<H3,     256>>>(W_ih0, 2*HD, 2*HD, pWih0h, 2048, 0, 1024, 1);  // B2
    k_cath<<<VOC,    128>>>(out_W,   HD,   HD, poWh,    512, 0, 0, 2);     // 1-term
    k_cath<<<TT2*NB, 128>>>(pX,      HD,   HD, pXavh,  2048, 0, 1024, 0);  // A2 (X part)

    // attention
    k_att_scores<<<dim3(TT2/8, NB), 256>>>(va_W, dout);
    k_attv<<<dim3(NB, TT2/32, HD/256), 256>>>(enc);
    k_cath<<<TT2*NB, 128>>>(pav, HD, HD, pXavh, 2048, 512, 1536, 0);       // A2 (av part)

    // gi0 = [X, att_v] @ W_ih0^T + b_ih0   (M=2048, N=1536, K'=2048)
    k_gemmh<<<dim3(H3/128, (TT2*NB)/128), 256>>>((const uint_t*)pXavh, 1024,
        (const uint_t*)pWih0h, 1024, b_ih0, pgi0, H3, 2048);

    // recurrence
    k_rec<<<NBLK, 256>>>(W_hh0, b_hh0, W_ih1, b_ih1, W_hh1, b_hh1);

    // y = ys @ out_W^T + out_b   (M=2048, N=32000, K=512, 1-term fp16)
    k_cath<<<TT2*NB, 128>>>(pys, HD, HD, pysh, 512, 0, 0, 2);
    k_gemmh<<<dim3(VOC/128, (TT2*NB)/128), 256>>>((const uint_t*)pysh, 256,
        (const uint_t*)poWh, 256, out_b, dout, VOC, 512);

    // final hidden states
    k_fin<<<(2*BHD + 255)/256, 256>>>(dout);
    (void)in_sizes; (void)n_in; (void)out_size;
}

// round 10
// speedup vs baseline: 1.2560x; 1.0612x over previous
#include <cuda_runtime.h>
#include <cuda_fp16.h>
#include <cstddef>
#include <cstdint>

#define HD   512
#define VOC  32000
#define TT1  128
#define TT2  64
#define NB   32
#define H3   1536
#define BHD  (NB*HD)
#define YSZ  ((size_t)TT2*NB*VOC)
#define HF_OFF YSZ
#define LS_OFF (YSZ + (size_t)2*BHD)

typedef unsigned int uint_t;

// ---------------- scratch (device globals; no runtime alloc) ----------------
__device__ float g_X  [TT2*NB*HD];
__device__ float g_q  [TT2*NB*HD];
__device__ float g_ep [TT1*NB*HD];
__device__ float g_sc [TT2*TT1*NB];
__device__ float g_av [TT2*NB*HD];
__device__ float g_gi0[TT2*NB*H3];
__device__ float g_ys [TT2*NB*HD];
__device__ float g_h0c[2*BHD];
__device__ float g_h1c[2*BHD];

// fp16 operands
__device__ __align__(16) __half h_ench [(size_t)TT1*NB * 1024];  // A2: [hi|lo]
__device__ __align__(16) __half h_Wxh  [512 * 1024];             // B2: [hi|hi]
__device__ __align__(16) __half h_Weh  [512 * 1024];             // B2
__device__ __align__(16) __half h_Xh   [(size_t)TT2*NB * 1024];  // A2
__device__ __align__(16) __half h_Xavh [(size_t)TT2*NB * 2048];  // A2 of [X|av]
__device__ __align__(16) __half h_Wih0h[(size_t)H3 * 2048];      // B2
__device__ __align__(16) __half h_oWh  [(size_t)VOC * 512];      // 1-term
__device__ __align__(16) __half h_ysh  [(size_t)TT2*NB * 512];   // 1-term

// grid barrier state
__device__ unsigned g_bgen = 0;
__device__ unsigned g_bcnt = 0;

__device__ __forceinline__ int CH(int b, int k){ return ((k>>2)<<7) + (b<<2) + (k&3); }

__device__ __forceinline__ float fast_tanh(float x){
    float e = __expf(2.f*x);
    return 1.f - __fdividef(2.f, e + 1.f);
}
__device__ __forceinline__ float fast_sig(float x){
    return __fdividef(1.f, 1.f + __expf(-x));
}

// ---------------- embed + state init ----------------
__global__ __launch_bounds__(256) void k_embed(const int* __restrict__ tok,
                                               const float* __restrict__ emb,
                                               const float* __restrict__ state)
{
    int i = blockIdx.x*256 + threadIdx.x;
    if (i < TT2*NB*HD){
        int row = i >> 9;
        int h   = i & (HD-1);
        g_X[i] = emb[(size_t)tok[row]*HD + h];
    }
    if (i < 2*BHD){
        int l = (i >= BHD);
        int r = i & (BHD-1);
        int b = r >> 9, h = r & (HD-1);
        float v = state[i];
        if (l == 0) g_h0c[CH(b,h)] = v;
        else        g_h1c[CH(b,h)] = v;
    }
}

// ---------------- fp32 -> fp16 split conversion ----------------
// mode 0 (A2): hi at off0, lo at off1 ; mode 1 (B2): hi at off0 and off1 ;
// mode 2: hi at off0 only.
__device__ __forceinline__ uint_t packh(__half a, __half b){
    return ((uint_t)__half_as_ushort(b) << 16) | (uint_t)__half_as_ushort(a);
}
__global__ void k_cath(const float* __restrict__ src, int src_ld, int Ksrc,
                       __half* __restrict__ dst, int dst_ld,
                       int off0, int off1, int mode)
{
    int row = blockIdx.x;
    for (int k = threadIdx.x*4; k < Ksrc; k += blockDim.x*4){
        float4 v = *reinterpret_cast<const float4*>(src + (size_t)row*src_ld + k);
        __half h0 = __float2half_rn(v.x), h1 = __float2half_rn(v.y);
        __half h2 = __float2half_rn(v.z), h3 = __float2half_rn(v.w);
        uint2 hv = make_uint2(packh(h0,h1), packh(h2,h3));
        *reinterpret_cast<uint2*>(dst + (size_t)row*dst_ld + off0 + k) = hv;
        if (mode == 0){
            __half l0 = __float2half_rn(v.x - __half2float(h0));
            __half l1 = __float2half_rn(v.y - __half2float(h1));
            __half l2 = __float2half_rn(v.z - __half2float(h2));
            __half l3 = __float2half_rn(v.w - __half2float(h3));
            uint2 lv = make_uint2(packh(l0,l1), packh(l2,l3));
            *reinterpret_cast<uint2*>(dst + (size_t)row*dst_ld + off1 + k) = lv;
        } else if (mode == 1){
            *reinterpret_cast<uint2*>(dst + (size_t)row*dst_ld + off1 + k) = hv;
        }
    }
}

// ---------------- fp16 GEMM: C[M,N] = A(M,K)*B(N,K)^T (+bias) ----------------
// 128x128 block tile, 8 warps (2M x 4N) of 64x32. Scalar-LDS fragments with
// XOR swizzle: element (P, row) stored at P*SKH + (row ^ ((P>>2)<<3)).
// Both STS and LDS phases are bank-conflict-free under this mapping.
__device__ __forceinline__ void mma16f(float* d, const uint_t* a, uint_t b0, uint_t b1){
    asm volatile("mma.sync.aligned.m16n8k16.row.col.f32.f16.f16.f32 "
        "{%0,%1,%2,%3}, {%4,%5,%6,%7}, {%8,%9}, {%0,%1,%2,%3};\n"
        : "+f"(d[0]), "+f"(d[1]), "+f"(d[2]), "+f"(d[3])
        : "r"(a[0]), "r"(a[1]), "r"(a[2]), "r"(a[3]), "r"(b0), "r"(b1));
}
#define SKH 136
#define SWZ(P,row) ((P)*SKH + ((row) ^ ((((P)>>2)&3)<<3)))

__global__ __launch_bounds__(256, 2) void k_gemmh(
    const uint_t* __restrict__ A, int lda,   // lda in uint (fp16x2) units = K/2
    const uint_t* __restrict__ B, int ldb,
    const float* __restrict__ bias,
    float* __restrict__ C, int ldc, int K)
{
    __shared__ uint_t sA[16*SKH], sB[16*SKH];
    const int m0 = blockIdx.y * 128;
    const int n0 = blockIdx.x * 128;
    const int tid = threadIdx.x, lane = tid & 31, warp = tid >> 5;
    const int wm = (warp & 1) * 64;
    const int wn = (warp >> 1) * 32;
    const int g  = lane >> 2, tg = lane & 3;

    float acc[4][4][4];
    #pragma unroll
    for (int i=0;i<4;i++)
        #pragma unroll
        for (int j=0;j<4;j++){ acc[i][j][0]=0.f; acc[i][j][1]=0.f; acc[i][j][2]=0.f; acc[i][j][3]=0.f; }

    for (int k0 = 0; k0 < K; k0 += 32){
        const int khu = k0 >> 1;          // uint col base
        #pragma unroll
        for (int i=0;i<2;i++){
            int idx = i*256 + tid;        // 0..511
            int row = idx >> 2;           // 0..127
            int p   = (idx & 3) * 4;      // uint index base within 16-uint chunk
            uint4 va = *reinterpret_cast<const uint4*>(A + (size_t)(m0+row)*lda + khu + p);
            sA[SWZ(p+0,row)] = va.x;  sA[SWZ(p+1,row)] = va.y;
            sA[SWZ(p+2,row)] = va.z;  sA[SWZ(p+3,row)] = va.w;
            uint4 vb = *reinterpret_cast<const uint4*>(B + (size_t)(n0+row)*ldb + khu + p);
            sB[SWZ(p+0,row)] = vb.x;  sB[SWZ(p+1,row)] = vb.y;
            sB[SWZ(p+2,row)] = vb.z;  sB[SWZ(p+3,row)] = vb.w;
        }
        __syncthreads();
        #pragma unroll
        for (int h2=0; h2<2; h2++){
            const int kb2 = h2*8;
            const int P0 = kb2 + tg;        // fragment k-uint index (low)
            const int P1 = kb2 + tg + 4;    // fragment k-uint index (high)
            #pragma unroll
            for (int mp=0; mp<2; mp++){
                uint_t ah[2][4];
                #pragma unroll
                for (int q=0;q<2;q++){
                    int r0 = wm + (mp*2+q)*16 + g;
                    ah[q][0]=sA[SWZ(P0,r0)];   ah[q][1]=sA[SWZ(P0,r0+8)];
                    ah[q][2]=sA[SWZ(P1,r0)];   ah[q][3]=sA[SWZ(P1,r0+8)];
                }
                #pragma unroll
                for (int ns=0; ns<4; ns++){
                    int col = wn + ns*8 + g;
                    uint_t b0 = sB[SWZ(P0,col)];
                    uint_t b1 = sB[SWZ(P1,col)];
                    #pragma unroll
                    for (int q=0;q<2;q++)
                        mma16f(acc[mp*2+q][ns], ah[q], b0, b1);
                }
            }
        }
        __syncthreads();
    }
    #pragma unroll
    for (int ms=0; ms<4; ms++){
        #pragma unroll
        for (int ns=0; ns<4; ns++){
            int r0  = m0 + wm + ms*16 + g;
            int col = n0 + wn + ns*8 + tg*2;
            float b0v = 0.f, b1v = 0.f;
            if (bias){ b0v = bias[col]; b1v = bias[col+1]; }
            float2 v0 = make_float2(acc[ms][ns][0]+b0v, acc[ms][ns][1]+b1v);
            float2 v1 = make_float2(acc[ms][ns][2]+b0v, acc[ms][ns][3]+b1v);
            *reinterpret_cast<float2*>(C + (size_t)r0*ldc + col)     = v0;
            *reinterpret_cast<float2*>(C + (size_t)(r0+8)*ldc + col) = v1;
        }
    }
}

// ---------------- attention logits + softmax ----------------
__global__ __launch_bounds__(256) void k_att_scores(const float* __restrict__ va,
                                                    float* __restrict__ dout)
{
    __shared__ float q8[8*HD];
    __shared__ float vsm[HD];
    __shared__ float esm[8*TT1];
    const int b   = blockIdx.y;
    const int t2b = blockIdx.x * 8;
    const int tid = threadIdx.x, lane = tid & 31, w = tid >> 5;

    for (int i = tid; i < 8*HD; i += 256){
        int t2i = i >> 9, h = i & (HD-1);
        q8[i] = g_q[((size_t)(t2b + t2i)*NB + b)*HD + h];
    }
    for (int i = tid; i < HD; i += 256) vsm[i] = va[i];
    __syncthreads();

    for (int t1 = w; t1 < TT1; t1 += 8){
        const float* ep = g_ep + ((size_t)t1*NB + b)*HD;
        float accv[8];
        #pragma unroll
        for (int i=0;i<8;i++) accv[i] = 0.f;
        for (int h = lane; h < HD; h += 32){
            float e  = ep[h];
            float vv = vsm[h];
            #pragma unroll
            for (int i=0;i<8;i++) accv[i] += vv * fast_tanh(q8[i*HD + h] + e);
        }
        #pragma unroll
        for (int i=0;i<8;i++){
            float s = accv[i];
            #pragma unroll
            for (int o=16;o;o>>=1) s += __shfl_xor_sync(0xffffffffu, s, o);
            if (lane == 0) esm[i*TT1 + t1] = s;
        }
    }
    __syncthreads();

    {
        float v[4];
        #pragma unroll
        for (int i=0;i<4;i++) v[i] = esm[w*TT1 + lane + 32*i];
        float m = fmaxf(fmaxf(v[0],v[1]), fmaxf(v[2],v[3]));
        #pragma unroll
        for (int o=16;o;o>>=1) m = fmaxf(m, __shfl_xor_sync(0xffffffffu, m, o));
        float s = 0.f;
        #pragma unroll
        for (int i=0;i<4;i++){ v[i] = __expf(v[i]-m); s += v[i]; }
        #pragma unroll
        for (int o=16;o;o>>=1) s += __shfl_xor_sync(0xffffffffu, s, o);
        float inv = __fdividef(1.f, s);
        int t2 = t2b + w;
        #pragma unroll
        for (int i=0;i<4;i++){
            int t1 = lane + 32*i;
            float sc = v[i]*inv;
            g_sc[((size_t)t2*TT1 + t1)*NB + b] = sc;
            if (t2 == TT2-1) dout[LS_OFF + (size_t)t1*NB + b] = sc;
        }
    }
}

// ---------------- attention values ----------------
__global__ __launch_bounds__(256) void k_attv(const float* __restrict__ enc)
{
    __shared__ float sst[TT1*32];
    const int b   = blockIdx.x;
    const int t2o = blockIdx.y * 32;
    const int h   = blockIdx.z * 256 + threadIdx.x;
    for (int i = threadIdx.x; i < 32*TT1; i += 256){
        int t1 = i >> 5, i2 = i & 31;
        sst[t1*32 + i2] = g_sc[((size_t)(t2o + i2)*TT1 + t1)*NB + b];
    }
    __syncthreads();
    float acc[32];
    #pragma unroll
    for (int i=0;i<32;i++) acc[i] = 0.f;
    for (int t1 = 0; t1 < TT1; t1++){
        float ev = enc[((size_t)t1*NB + b)*HD + h];
        #pragma unroll
        for (int i=0;i<32;i++) acc[i] += ev * sst[t1*32 + i];
    }
    #pragma unroll
    for (int i=0;i<32;i++)
        g_av[((size_t)(t2o+i)*NB + b)*HD + h] = acc[i];
}

// ---------------- persistent recurrence ----------------
__device__ __forceinline__ void dot3(const float* __restrict__ W, int j,
                                     const float* __restrict__ hch, int b,
                                     float& s0, float& s1, float& s2)
{
    const float* w0 = W + (size_t) j        *HD;
    const float* w1 = W + (size_t)(j+ 512)  *HD;
    const float* w2 = W + (size_t)(j+1024)  *HD;
    float a0=0.f, a1=0.f, a2=0.f;
    #pragma unroll 4
    for (int k = 0; k < HD; k += 4){
        float4 hv = __ldcg(reinterpret_cast<const float4*>(hch + ((k>>2)<<7) + (b<<2)));
        float4 x = *reinterpret_cast<const float4*>(w0 + k);
        float4 y = *reinterpret_cast<const float4*>(w1 + k);
        float4 z = *reinterpret_cast<const float4*>(w2 + k);
        a0 += x.x*hv.x + x.y*hv.y + x.z*hv.z + x.w*hv.w;
        a1 += y.x*hv.x + y.y*hv.y + y.z*hv.z + y.w*hv.w;
        a2 += z.x*hv.x + z.y*hv.y + z.z*hv.z + z.w*hv.w;
    }
    s0 = a0; s1 = a1; s2 = a2;
}

#define NBLK 192

__global__ __launch_bounds__(256, 2) void k_rec(
    const float* __restrict__ W_hh0, const float* __restrict__ b_hh0,
    const float* __restrict__ W_ih1, const float* __restrict__ b_ih1,
    const float* __restrict__ W_hh1, const float* __restrict__ b_hh1)
{
    const int blk  = blockIdx.x;
    const int warp = threadIdx.x >> 5;
    const int b    = threadIdx.x & 31;
    __shared__ float sm[8][3][32];
    __shared__ unsigned s_gen;
    if (threadIdx.x == 0) s_gen = atomicAdd(&g_bgen, 0u);
    __syncthreads();
    const unsigned G0 = s_gen;

    for (int t = 0; t <= TT2; t++){
        if (blk < 64){
            if (t < TT2){
                const int j = blk*8 + warp;
                const int p = t & 1;
                const float* hch = g_h0c + p*BHD;
                float s0, s1, s2;
                dot3(W_hh0, j, hch, b, s0, s1, s2);
                const float* gi = g_gi0 + ((size_t)t*NB + b)*H3;
                float r = fast_sig (gi[j      ] + s0 + b_hh0[j      ]);
                float z = fast_sig (gi[j+ 512] + s1 + b_hh0[j+ 512]);
                float n = fast_tanh(gi[j+1024] + r*(s2 + b_hh0[j+1024]));
                float hold = __ldcg(&hch[CH(b,j)]);
                __stcg(&g_h0c[(1-p)*BHD + CH(b,j)], (1.f-z)*n + z*hold);
            }
        } else {
            if (t >= 1){
                const int s    = t - 1;
                const int blk2 = blk - 64;
                const int j    = blk2*4 + (warp >> 1);
                const int mat  = warp & 1;
                const int p1   = s & 1;
                const float* hin = (mat == 0) ? (g_h0c + ((s+1)&1)*BHD)
                                              : (g_h1c + p1*BHD);
                const float* W   = (mat == 0) ? W_ih1 : W_hh1;
                float s0, s1, s2;
                dot3(W, j, hin, b, s0, s1, s2);
                sm[warp][0][b] = s0; sm[warp][1][b] = s1; sm[warp][2][b] = s2;
                __syncthreads();
                if (mat == 0){
                    float xr = s0 + b_ih1[j      ];
                    float xz = s1 + b_ih1[j+ 512];
                    float xn = s2 + b_ih1[j+1024];
                    float hr = sm[warp+1][0][b] + b_hh1[j      ];
                    float hz = sm[warp+1][1][b] + b_hh1[j+ 512];
                    float hn = sm[warp+1][2][b] + b_hh1[j+1024];
                    float r = fast_sig(xr + hr);
                    float z = fast_sig(xz + hz);
                    float n = fast_tanh(xn + r*hn);
                    float h1old = __ldcg(&g_h1c[p1*BHD + CH(b,j)]);
                    float hnew = (1.f-z)*n + z*h1old;
                    __stcg(&g_h1c[((s+1)&1)*BHD + CH(b,j)], hnew);
                    g_ys[((size_t)s*NB + b)*HD + j] = hnew;
                }
            }
        }
        if (t == TT2) break;
        __syncthreads();
        if (threadIdx.x == 0){
            __threadfence();
            unsigned a = atomicAdd(&g_bcnt, 1u);
            if (a == NBLK-1u){
                atomicExch(&g_bcnt, 0u);
                __threadfence();
                atomicAdd(&g_bgen, 1u);
            } else {
                unsigned target = G0 + (unsigned)t + 1u;
                while ((int)(*(volatile unsigned*)&g_bgen - target) < 0) __nanosleep(64);
            }
            __threadfence();
        }
        __syncthreads();
    }
}

// ---------------- final state copy ----------------
__global__ __launch_bounds__(256) void k_fin(float* __restrict__ dout)
{
    int i = blockIdx.x*256 + threadIdx.x;
    if (i >= 2*BHD) return;
    int l = (i >= BHD);
    int r = i & (BHD-1);
    int b = r >> 9, h = r & (HD-1);
    float v = l ? g_h1c[CH(b,h)] : g_h0c[CH(b,h)];
    dout[HF_OFF + i] = v;
}

extern "C" void kernel_launch(void* const* d_in, const int* in_sizes, int n_in,
                              void* d_out, int out_size)
{
    const int*   tok   = (const int*)  d_in[0];
    const float* state = (const float*)d_in[1];
    const float* enc   = (const float*)d_in[2];
    const float* emb   = (const float*)d_in[3];
    const float* wa_W  = (const float*)d_in[4];
    const float* wa_b  = (const float*)d_in[5];
    const float* va_W  = (const float*)d_in[6];
    const float* W_ih0 = (const float*)d_in[7];
    const float* W_hh0 = (const float*)d_in[8];
    const float* b_ih0 = (const float*)d_in[9];
    const float* b_hh0 = (const float*)d_in[10];
    const float* W_ih1 = (const float*)d_in[11];
    const float* W_hh1 = (const float*)d_in[12];
    const float* b_ih1 = (const float*)d_in[13];
    const float* b_hh1 = (const float*)d_in[14];
    const float* out_W = (const float*)d_in[15];
    const float* out_b = (const float*)d_in[16];
    float* dout = (float*)d_out;

    float *pX, *pep, *pq, *pav, *pgi0, *pys;
    __half *pench, *pWxh, *pWeh, *pXh, *pXavh, *pWih0h, *poWh, *pysh;
    cudaGetSymbolAddress((void**)&pX,     g_X);
    cudaGetSymbolAddress((void**)&pep,    g_ep);
    cudaGetSymbolAddress((void**)&pq,     g_q);
    cudaGetSymbolAddress((void**)&pav,    g_av);
    cudaGetSymbolAddress((void**)&pgi0,   g_gi0);
    cudaGetSymbolAddress((void**)&pys,    g_ys);
    cudaGetSymbolAddress((void**)&pench,  h_ench);
    cudaGetSymbolAddress((void**)&pWxh,   h_Wxh);
    cudaGetSymbolAddress((void**)&pWeh,   h_Weh);
    cudaGetSymbolAddress((void**)&pXh,    h_Xh);
    cudaGetSymbolAddress((void**)&pXavh,  h_Xavh);
    cudaGetSymbolAddress((void**)&pWih0h, h_Wih0h);
    cudaGetSymbolAddress((void**)&poWh,   h_oWh);
    cudaGetSymbolAddress((void**)&pysh,   h_ysh);

    // --- launch order: my launch #4 is the enc_proj GEMM (ncu lands there) ---
    // 1. embed + state init
    k_embed<<<(TT2*NB*HD + 255)/256, 256>>>(tok, emb, state);
    // 2-3. conversions needed by enc_proj
    k_cath<<<TT1*NB, 128>>>(enc,        HD, HD, pench, 1024, 0, 512, 0);   // A2
    k_cath<<<512,    128>>>(wa_W + HD, 2*HD, HD, pWeh, 1024, 0, 512, 1);   // B2
    // 4. enc_proj = enc @ We^T + wa_b   (M=4096, N=512, K'=1024)  << profiled
    k_gemmh<<<dim3(HD/128, (TT1*NB)/128), 256>>>((const uint_t*)pench, 512,
        (const uint_t*)pWeh, 512, wa_b, pep, HD, 1024);
    // 5-6. conversions for q
    k_cath<<<512,    128>>>(wa_W,      2*HD, HD, pWxh, 1024, 0, 512, 1);   // B2
    k_cath<<<TT2*NB, 128>>>(pX,         HD, HD, pXh,  1024, 0, 512, 0);    // A2
    // 7. q = X @ Wx^T                   (M=2048, N=512, K'=1024)
    k_gemmh<<<dim3(HD/128, (TT2*NB)/128), 256>>>((const uint_t*)pXh, 512,
        (const uint_t*)pWxh, 512, nullptr, pq, HD, 1024);

    // remaining conversions
    k_cath<<<H3,     256>>>(W_ih0, 2*HD, 2*HD, pWih0h, 2048, 0, 1024, 1);  // B2
    k_cath<<<VOC,    128>>>(out_W,   HD,   HD, poWh,    512, 0, 0, 2);     // 1-term
    k_cath<<<TT2*NB, 128>>>(pX,      HD,   HD, pXavh,  2048, 0, 1024, 0);  // A2 (X part)

    // attention
    k_att_scores<<<dim3(TT2/8, NB), 256>>>(va_W, dout);
    k_attv<<<dim3(NB, TT2/32, HD/256), 256>>>(enc);
    k_cath<<<TT2*NB, 128>>>(pav, HD, HD, pXavh, 2048, 512, 1536, 0);       // A2 (av part)

    // gi0 = [X, att_v] @ W_ih0^T + b_ih0   (M=2048, N=1536, K'=2048)
    k_gemmh<<<dim3(H3/128, (TT2*NB)/128), 256>>>((const uint_t*)pXavh, 1024,
        (const uint_t*)pWih0h, 1024, b_ih0, pgi0, H3, 2048);

    // recurrence
    k_rec<<<NBLK, 256>>>(W_hh0, b_hh0, W_ih1, b_ih1, W_hh1, b_hh1);

    // y = ys @ out_W^T + out_b   (M=2048, N=32000, K=512, 1-term fp16)
    k_cath<<<TT2*NB, 128>>>(pys, HD, HD, pysh, 512, 0, 0, 2);
    k_gemmh<<<dim3(VOC/128, (TT2*NB)/128), 256>>>((const uint_t*)pysh, 256,
        (const uint_t*)poWh, 256, out_b, dout, VOC, 512);

    // final hidden states
    k_fin<<<(2*BHD + 255)/256, 256>>>(dout);
    (void)in_sizes; (void)n_in; (void)out_size;
}

// round 11
// speedup vs baseline: 1.2634x; 1.0058x over previous
#include <cuda_runtime.h>
#include <cuda_fp16.h>
#include <cstddef>
#include <cstdint>

#define HD   512
#define VOC  32000
#define TT1  128
#define TT2  64
#define NB   32
#define H3   1536
#define BHD  (NB*HD)
#define YSZ  ((size_t)TT2*NB*VOC)
#define HF_OFF YSZ
#define LS_OFF (YSZ + (size_t)2*BHD)

typedef unsigned int uint_t;

// ---------------- scratch (device globals; no runtime alloc) ----------------
__device__ float g_X  [TT2*NB*HD];
__device__ float g_q  [TT2*NB*HD];
__device__ float g_ep [TT1*NB*HD];
__device__ float g_sc [TT2*TT1*NB];
__device__ float g_av [TT2*NB*HD];
__device__ float g_gi0[TT2*NB*H3];
__device__ float g_ys [TT2*NB*HD];
__device__ float g_h0c[2*BHD];
__device__ float g_h1c[2*BHD];

// fp16 operands
__device__ __align__(16) __half h_ench [(size_t)TT1*NB * 1024];  // A2: [hi|lo]
__device__ __align__(16) __half h_Wxh  [512 * 1024];             // B2: [hi|hi]
__device__ __align__(16) __half h_Weh  [512 * 1024];             // B2
__device__ __align__(16) __half h_Xh   [(size_t)TT2*NB * 1024];  // A2
__device__ __align__(16) __half h_Xavh [(size_t)TT2*NB * 2048];  // A2 of [X|av]
__device__ __align__(16) __half h_Wih0h[(size_t)H3 * 2048];      // B2
__device__ __align__(16) __half h_oWh  [(size_t)VOC * 512];      // 1-term
__device__ __align__(16) __half h_ysh  [(size_t)TT2*NB * 512];   // 1-term

// grid barrier state (monotonic; reset by k_embed each launch)
__device__ unsigned g_bcnt = 0;

__device__ __forceinline__ int CH(int b, int k){ return ((k>>2)<<7) + (b<<2) + (k&3); }

__device__ __forceinline__ float fast_tanh(float x){
    float e = __expf(2.f*x);
    return 1.f - __fdividef(2.f, e + 1.f);
}
__device__ __forceinline__ float fast_sig(float x){
    return __fdividef(1.f, 1.f + __expf(-x));
}

// ---------------- embed + state init + barrier reset ----------------
__global__ __launch_bounds__(256) void k_embed(const int* __restrict__ tok,
                                               const float* __restrict__ emb,
                                               const float* __restrict__ state)
{
    int i = blockIdx.x*256 + threadIdx.x;
    if (i == 0) g_bcnt = 0;
    if (i < TT2*NB*HD){
        int row = i >> 9;
        int h   = i & (HD-1);
        g_X[i] = emb[(size_t)tok[row]*HD + h];
    }
    if (i < 2*BHD){
        int l = (i >= BHD);
        int r = i & (BHD-1);
        int b = r >> 9, h = r & (HD-1);
        float v = state[i];
        if (l == 0) g_h0c[CH(b,h)] = v;
        else        g_h1c[CH(b,h)] = v;
    }
}

// ---------------- fp32 -> fp16 split conversion ----------------
__device__ __forceinline__ uint_t packh(__half a, __half b){
    return ((uint_t)__half_as_ushort(b) << 16) | (uint_t)__half_as_ushort(a);
}
__global__ void k_cath(const float* __restrict__ src, int src_ld, int Ksrc,
                       __half* __restrict__ dst, int dst_ld,
                       int off0, int off1, int mode)
{
    int row = blockIdx.x;
    for (int k = threadIdx.x*4; k < Ksrc; k += blockDim.x*4){
        float4 v = *reinterpret_cast<const float4*>(src + (size_t)row*src_ld + k);
        __half h0 = __float2half_rn(v.x), h1 = __float2half_rn(v.y);
        __half h2 = __float2half_rn(v.z), h3 = __float2half_rn(v.w);
        uint2 hv = make_uint2(packh(h0,h1), packh(h2,h3));
        *reinterpret_cast<uint2*>(dst + (size_t)row*dst_ld + off0 + k) = hv;
        if (mode == 0){
            __half l0 = __float2half_rn(v.x - __half2float(h0));
            __half l1 = __float2half_rn(v.y - __half2float(h1));
            __half l2 = __float2half_rn(v.z - __half2float(h2));
            __half l3 = __float2half_rn(v.w - __half2float(h3));
            uint2 lv = make_uint2(packh(l0,l1), packh(l2,l3));
            *reinterpret_cast<uint2*>(dst + (size_t)row*dst_ld + off1 + k) = lv;
        } else if (mode == 1){
            *reinterpret_cast<uint2*>(dst + (size_t)row*dst_ld + off1 + k) = hv;
        }
    }
}

// ---------------- fp16 GEMM (unchanged from R10, swizzled scalar LDS) --------
__device__ __forceinline__ void mma16f(float* d, const uint_t* a, uint_t b0, uint_t b1){
    asm volatile("mma.sync.aligned.m16n8k16.row.col.f32.f16.f16.f32 "
        "{%0,%1,%2,%3}, {%4,%5,%6,%7}, {%8,%9}, {%0,%1,%2,%3};\n"
        : "+f"(d[0]), "+f"(d[1]), "+f"(d[2]), "+f"(d[3])
        : "r"(a[0]), "r"(a[1]), "r"(a[2]), "r"(a[3]), "r"(b0), "r"(b1));
}
#define SKH 136
#define SWZ(P,row) ((P)*SKH + ((row) ^ ((((P)>>2)&3)<<3)))

__global__ __launch_bounds__(256, 2) void k_gemmh(
    const uint_t* __restrict__ A, int lda,
    const uint_t* __restrict__ B, int ldb,
    const float* __restrict__ bias,
    float* __restrict__ C, int ldc, int K)
{
    __shared__ uint_t sA[16*SKH], sB[16*SKH];
    const int m0 = blockIdx.y * 128;
    const int n0 = blockIdx.x * 128;
    const int tid = threadIdx.x, lane = tid & 31, warp = tid >> 5;
    const int wm = (warp & 1) * 64;
    const int wn = (warp >> 1) * 32;
    const int g  = lane >> 2, tg = lane & 3;

    float acc[4][4][4];
    #pragma unroll
    for (int i=0;i<4;i++)
        #pragma unroll
        for (int j=0;j<4;j++){ acc[i][j][0]=0.f; acc[i][j][1]=0.f; acc[i][j][2]=0.f; acc[i][j][3]=0.f; }

    for (int k0 = 0; k0 < K; k0 += 32){
        const int khu = k0 >> 1;
        #pragma unroll
        for (int i=0;i<2;i++){
            int idx = i*256 + tid;
            int row = idx >> 2;
            int p   = (idx & 3) * 4;
            uint4 va = *reinterpret_cast<const uint4*>(A + (size_t)(m0+row)*lda + khu + p);
            sA[SWZ(p+0,row)] = va.x;  sA[SWZ(p+1,row)] = va.y;
            sA[SWZ(p+2,row)] = va.z;  sA[SWZ(p+3,row)] = va.w;
            uint4 vb = *reinterpret_cast<const uint4*>(B + (size_t)(n0+row)*ldb + khu + p);
            sB[SWZ(p+0,row)] = vb.x;  sB[SWZ(p+1,row)] = vb.y;
            sB[SWZ(p+2,row)] = vb.z;  sB[SWZ(p+3,row)] = vb.w;
        }
        __syncthreads();
        #pragma unroll
        for (int h2=0; h2<2; h2++){
            const int kb2 = h2*8;
            const int P0 = kb2 + tg;
            const int P1 = kb2 + tg + 4;
            #pragma unroll
            for (int mp=0; mp<2; mp++){
                uint_t ah[2][4];
                #pragma unroll
                for (int q=0;q<2;q++){
                    int r0 = wm + (mp*2+q)*16 + g;
                    ah[q][0]=sA[SWZ(P0,r0)];   ah[q][1]=sA[SWZ(P0,r0+8)];
                    ah[q][2]=sA[SWZ(P1,r0)];   ah[q][3]=sA[SWZ(P1,r0+8)];
                }
                #pragma unroll
                for (int ns=0; ns<4; ns++){
                    int col = wn + ns*8 + g;
                    uint_t b0 = sB[SWZ(P0,col)];
                    uint_t b1 = sB[SWZ(P1,col)];
                    #pragma unroll
                    for (int q=0;q<2;q++)
                        mma16f(acc[mp*2+q][ns], ah[q], b0, b1);
                }
            }
        }
        __syncthreads();
    }
    #pragma unroll
    for (int ms=0; ms<4; ms++){
        #pragma unroll
        for (int ns=0; ns<4; ns++){
            int r0  = m0 + wm + ms*16 + g;
            int col = n0 + wn + ns*8 + tg*2;
            float b0v = 0.f, b1v = 0.f;
            if (bias){ b0v = bias[col]; b1v = bias[col+1]; }
            float2 v0 = make_float2(acc[ms][ns][0]+b0v, acc[ms][ns][1]+b1v);
            float2 v1 = make_float2(acc[ms][ns][2]+b0v, acc[ms][ns][3]+b1v);
            *reinterpret_cast<float2*>(C + (size_t)r0*ldc + col)     = v0;
            *reinterpret_cast<float2*>(C + (size_t)(r0+8)*ldc + col) = v1;
        }
    }
}

// ---------------- attention logits + softmax ----------------
__global__ __launch_bounds__(256) void k_att_scores(const float* __restrict__ va,
                                                    float* __restrict__ dout)
{
    __shared__ float q8[8*HD];
    __shared__ float vsm[HD];
    __shared__ float esm[8*TT1];
    const int b   = blockIdx.y;
    const int t2b = blockIdx.x * 8;
    const int tid = threadIdx.x, lane = tid & 31, w = tid >> 5;

    for (int i = tid; i < 8*HD; i += 256){
        int t2i = i >> 9, h = i & (HD-1);
        q8[i] = g_q[((size_t)(t2b + t2i)*NB + b)*HD + h];
    }
    for (int i = tid; i < HD; i += 256) vsm[i] = va[i];
    __syncthreads();

    for (int t1 = w; t1 < TT1; t1 += 8){
        const float* ep = g_ep + ((size_t)t1*NB + b)*HD;
        float accv[8];
        #pragma unroll
        for (int i=0;i<8;i++) accv[i] = 0.f;
        for (int h = lane; h < HD; h += 32){
            float e  = ep[h];
            float vv = vsm[h];
            #pragma unroll
            for (int i=0;i<8;i++) accv[i] += vv * fast_tanh(q8[i*HD + h] + e);
        }
        #pragma unroll
        for (int i=0;i<8;i++){
            float s = accv[i];
            #pragma unroll
            for (int o=16;o;o>>=1) s += __shfl_xor_sync(0xffffffffu, s, o);
            if (lane == 0) esm[i*TT1 + t1] = s;
        }
    }
    __syncthreads();

    {
        float v[4];
        #pragma unroll
        for (int i=0;i<4;i++) v[i] = esm[w*TT1 + lane + 32*i];
        float m = fmaxf(fmaxf(v[0],v[1]), fmaxf(v[2],v[3]));
        #pragma unroll
        for (int o=16;o;o>>=1) m = fmaxf(m, __shfl_xor_sync(0xffffffffu, m, o));
        float s = 0.f;
        #pragma unroll
        for (int i=0;i<4;i++){ v[i] = __expf(v[i]-m); s += v[i]; }
        #pragma unroll
        for (int o=16;o;o>>=1) s += __shfl_xor_sync(0xffffffffu, s, o);
        float inv = __fdividef(1.f, s);
        int t2 = t2b + w;
        #pragma unroll
        for (int i=0;i<4;i++){
            int t1 = lane + 32*i;
            float sc = v[i]*inv;
            g_sc[((size_t)t2*TT1 + t1)*NB + b] = sc;
            if (t2 == TT2-1) dout[LS_OFF + (size_t)t1*NB + b] = sc;
        }
    }
}

// ---------------- attention values ----------------
__global__ __launch_bounds__(256) void k_attv(const float* __restrict__ enc)
{
    __shared__ float sst[TT1*32];
    const int b   = blockIdx.x;
    const int t2o = blockIdx.y * 32;
    const int h   = blockIdx.z * 256 + threadIdx.x;
    for (int i = threadIdx.x; i < 32*TT1; i += 256){
        int t1 = i >> 5, i2 = i & 31;
        sst[t1*32 + i2] = g_sc[((size_t)(t2o + i2)*TT1 + t1)*NB + b];
    }
    __syncthreads();
    float acc[32];
    #pragma unroll
    for (int i=0;i<32;i++) acc[i] = 0.f;
    for (int t1 = 0; t1 < TT1; t1++){
        float ev = enc[((size_t)t1*NB + b)*HD + h];
        #pragma unroll
        for (int i=0;i<32;i++) acc[i] += ev * sst[t1*32 + i];
    }
    #pragma unroll
    for (int i=0;i<32;i++)
        g_av[((size_t)(t2o+i)*NB + b)*HD + h] = acc[i];
}

// ---------------- persistent recurrence v2: smem-staged h ----------------
// grid = 192 blocks (64 gru0 + 128 gru1), 2 blocks/SM guaranteed.
// Each step: block stages the h vector(s) it needs into 64KB dynamic smem
// (gru1: two vectors in two k-half phases), warps read via LDS.128.
#define NBLK 192

// dot of rows (j, j+512, j+1024) of W against smem-chunked h, k in [kb, kb+kn)
__device__ __forceinline__ void dotsm(const float* __restrict__ W, int j,
                                      const float* __restrict__ shb, int b,
                                      int kb, int kn,
                                      float& s0, float& s1, float& s2)
{
    const float* w0 = W + (size_t) j        *HD + kb;
    const float* w1 = W + (size_t)(j+ 512)  *HD + kb;
    const float* w2 = W + (size_t)(j+1024)  *HD + kb;
    float a0=s0, a1=s1, a2=s2;
    #pragma unroll 8
    for (int kk = 0; kk < kn; kk += 4){
        float4 hv = *reinterpret_cast<const float4*>(shb + ((kk>>2)<<7) + (b<<2));
        float4 x = *reinterpret_cast<const float4*>(w0 + kk);
        float4 y = *reinterpret_cast<const float4*>(w1 + kk);
        float4 z = *reinterpret_cast<const float4*>(w2 + kk);
        a0 += x.x*hv.x + x.y*hv.y + x.z*hv.z + x.w*hv.w;
        a1 += y.x*hv.x + y.y*hv.y + y.z*hv.z + y.w*hv.w;
        a2 += z.x*hv.x + z.y*hv.y + z.z*hv.z + z.w*hv.w;
    }
    s0 = a0; s1 = a1; s2 = a2;
}

__global__ __launch_bounds__(256, 2) void k_rec(
    const float* __restrict__ W_hh0, const float* __restrict__ b_hh0,
    const float* __restrict__ W_ih1, const float* __restrict__ b_ih1,
    const float* __restrict__ W_hh1, const float* __restrict__ b_hh1)
{
    extern __shared__ float sh[];       // 16384 floats (64 KB)
    __shared__ float sm[8][3][32];
    const int blk  = blockIdx.x;
    const int tid  = threadIdx.x;
    const int warp = tid >> 5;
    const int b    = tid & 31;

    for (int t = 0; t <= TT2; t++){
        if (blk < 64){
            if (t < TT2){
                // ---- gru0 at time t: stage full h0 (parity t&1) ----
                const float* sp = g_h0c + (t&1)*BHD;
                #pragma unroll
                for (int i = tid*4; i < BHD; i += 1024)
                    *reinterpret_cast<float4*>(sh + i) =
                        __ldcg(reinterpret_cast<const float4*>(sp + i));
                __syncthreads();
                const int j = blk*8 + warp;
                float s0=0.f, s1=0.f, s2=0.f;
                dotsm(W_hh0, j, sh, b, 0, HD, s0, s1, s2);
                const float* gi = g_gi0 + ((size_t)t*NB + b)*H3;
                float r = fast_sig (gi[j      ] + s0 + b_hh0[j      ]);
                float z = fast_sig (gi[j+ 512] + s1 + b_hh0[j+ 512]);
                float n = fast_tanh(gi[j+1024] + r*(s2 + b_hh0[j+1024]));
                float hold = sh[CH(b,j)];
                __stcg(&g_h0c[(1-(t&1))*BHD + CH(b,j)], (1.f-z)*n + z*hold);
            }
        } else {
            if (t >= 1){
                // ---- gru1 at time s = t-1: two k-half phases ----
                const int s    = t - 1;
                const int blk2 = blk - 64;
                const int j    = blk2*4 + (warp >> 1);
                const int mat  = warp & 1;               // 0: W_ih1*h0new, 1: W_hh1*h1old
                const int p1   = s & 1;
                const float* W = (mat == 0) ? W_ih1 : W_hh1;
                float s0=0.f, s1=0.f, s2=0.f;
                #pragma unroll
                for (int ph = 0; ph < 2; ph++){
                    const float* h0src = g_h0c + (t&1)*BHD + ph*8192;
                    const float* h1src = g_h1c + p1  *BHD + ph*8192;
                    #pragma unroll
                    for (int i = tid*4; i < 8192; i += 1024){
                        *reinterpret_cast<float4*>(sh + i) =
                            __ldcg(reinterpret_cast<const float4*>(h0src + i));
                        *reinterpret_cast<float4*>(sh + 8192 + i) =
                            __ldcg(reinterpret_cast<const float4*>(h1src + i));
                    }
                    __syncthreads();
                    dotsm(W, j, sh + mat*8192, b, ph*256, 256, s0, s1, s2);
                    __syncthreads();    // all warps done before next-phase overwrite
                }
                sm[warp][0][b] = s0; sm[warp][1][b] = s1; sm[warp][2][b] = s2;
                __syncthreads();
                if (mat == 0){
                    float xr = s0 + b_ih1[j      ];
                    float xz = s1 + b_ih1[j+ 512];
                    float xn = s2 + b_ih1[j+1024];
                    float hr = sm[warp+1][0][b] + b_hh1[j      ];
                    float hz = sm[warp+1][1][b] + b_hh1[j+ 512];
                    float hn = sm[warp+1][2][b] + b_hh1[j+1024];
                    float r = fast_sig(xr + hr);
                    float z = fast_sig(xz + hz);
                    float n = fast_tanh(xn + r*hn);
                    float h1old = __ldcg(&g_h1c[p1*BHD + CH(b,j)]);
                    float hnew = (1.f-z)*n + z*h1old;
                    __stcg(&g_h1c[((s+1)&1)*BHD + CH(b,j)], hnew);
                    g_ys[((size_t)s*NB + b)*HD + j] = hnew;
                }
            }
        }
        if (t == TT2) break;
        // ---- grid barrier: monotonic count, target (t+1)*NBLK ----
        __syncthreads();
        if (tid == 0){
            __threadfence();
            atomicAdd(&g_bcnt, 1u);
            unsigned tgt = (unsigned)(t + 1) * NBLK;
            while (__ldcg(&g_bcnt) < tgt) __nanosleep(64);
            __threadfence();
        }
        __syncthreads();
    }
}

// ---------------- final state copy ----------------
__global__ __launch_bounds__(256) void k_fin(float* __restrict__ dout)
{
    int i = blockIdx.x*256 + threadIdx.x;
    if (i >= 2*BHD) return;
    int l = (i >= BHD);
    int r = i & (BHD-1);
    int b = r >> 9, h = r & (HD-1);
    float v = l ? g_h1c[CH(b,h)] : g_h0c[CH(b,h)];
    dout[HF_OFF + i] = v;
}

extern "C" void kernel_launch(void* const* d_in, const int* in_sizes, int n_in,
                              void* d_out, int out_size)
{
    const int*   tok   = (const int*)  d_in[0];
    const float* state = (const float*)d_in[1];
    const float* enc   = (const float*)d_in[2];
    const float* emb   = (const float*)d_in[3];
    const float* wa_W  = (const float*)d_in[4];
    const float* wa_b  = (const float*)d_in[5];
    const float* va_W  = (const float*)d_in[6];
    const float* W_ih0 = (const float*)d_in[7];
    const float* W_hh0 = (const float*)d_in[8];
    const float* b_ih0 = (const float*)d_in[9];
    const float* b_hh0 = (const float*)d_in[10];
    const float* W_ih1 = (const float*)d_in[11];
    const float* W_hh1 = (const float*)d_in[12];
    const float* b_ih1 = (const float*)d_in[13];
    const float* b_hh1 = (const float*)d_in[14];
    const float* out_W = (const float*)d_in[15];
    const float* out_b = (const float*)d_in[16];
    float* dout = (float*)d_out;

    float *pX, *pep, *pq, *pav, *pgi0, *pys;
    __half *pench, *pWxh, *pWeh, *pXh, *pXavh, *pWih0h, *poWh, *pysh;
    cudaGetSymbolAddress((void**)&pX,     g_X);
    cudaGetSymbolAddress((void**)&pep,    g_ep);
    cudaGetSymbolAddress((void**)&pq,     g_q);
    cudaGetSymbolAddress((void**)&pav,    g_av);
    cudaGetSymbolAddress((void**)&pgi0,   g_gi0);
    cudaGetSymbolAddress((void**)&pys,    g_ys);
    cudaGetSymbolAddress((void**)&pench,  h_ench);
    cudaGetSymbolAddress((void**)&pWxh,   h_Wxh);
    cudaGetSymbolAddress((void**)&pWeh,   h_Weh);
    cudaGetSymbolAddress((void**)&pXh,    h_Xh);
    cudaGetSymbolAddress((void**)&pXavh,  h_Xavh);
    cudaGetSymbolAddress((void**)&pWih0h, h_Wih0h);
    cudaGetSymbolAddress((void**)&poWh,   h_oWh);
    cudaGetSymbolAddress((void**)&pysh,   h_ysh);

    cudaFuncSetAttribute(k_rec, cudaFuncAttributeMaxDynamicSharedMemorySize, 65536);

    // --- launch order: my launch #4 is the enc_proj GEMM (ncu lands there) ---
    // 1. embed + state init + barrier reset
    k_embed<<<(TT2*NB*HD + 255)/256, 256>>>(tok, emb, state);
    // 2-3. conversions needed by enc_proj
    k_cath<<<TT1*NB, 128>>>(enc,        HD, HD, pench, 1024, 0, 512, 0);   // A2
    k_cath<<<512,    128>>>(wa_W + HD, 2*HD, HD, pWeh, 1024, 0, 512, 1);   // B2
    // 4. enc_proj = enc @ We^T + wa_b   (M=4096, N=512, K'=1024)  << profiled
    k_gemmh<<<dim3(HD/128, (TT1*NB)/128), 256>>>((const uint_t*)pench, 512,
        (const uint_t*)pWeh, 512, wa_b, pep, HD, 1024);
    // 5-6. conversions for q
    k_cath<<<512,    128>>>(wa_W,      2*HD, HD, pWxh, 1024, 0, 512, 1);   // B2
    k_cath<<<TT2*NB, 128>>>(pX,         HD, HD, pXh,  1024, 0, 512, 0);    // A2
    // 7. q = X @ Wx^T                   (M=2048, N=512, K'=1024)
    k_gemmh<<<dim3(HD/128, (TT2*NB)/128), 256>>>((const uint_t*)pXh, 512,
        (const uint_t*)pWxh, 512, nullptr, pq, HD, 1024);

    // remaining conversions
    k_cath<<<H3,     256>>>(W_ih0, 2*HD, 2*HD, pWih0h, 2048, 0, 1024, 1);  // B2
    k_cath<<<VOC,    128>>>(out_W,   HD,   HD, poWh,    512, 0, 0, 2);     // 1-term
    k_cath<<<TT2*NB, 128>>>(pX,      HD,   HD, pXavh,  2048, 0, 1024, 0);  // A2 (X part)

    // attention
    k_att_scores<<<dim3(TT2/8, NB), 256>>>(va_W, dout);
    k_attv<<<dim3(NB, TT2/32, HD/256), 256>>>(enc);
    k_cath<<<TT2*NB, 128>>>(pav, HD, HD, pXavh, 2048, 512, 1536, 0);       // A2 (av part)

    // gi0 = [X, att_v] @ W_ih0^T + b_ih0   (M=2048, N=1536, K'=2048)
    k_gemmh<<<dim3(H3/128, (TT2*NB)/128), 256>>>((const uint_t*)pXavh, 1024,
        (const uint_t*)pWih0h, 1024, b_ih0, pgi0, H3, 2048);

    // recurrence (64KB dynamic smem per block)
    k_rec<<<NBLK, 256, 65536>>>(W_hh0, b_hh0, W_ih1, b_ih1, W_hh1, b_hh1);

    // y = ys @ out_W^T + out_b   (M=2048, N=32000, K=512, 1-term fp16)
    k_cath<<<TT2*NB, 128>>>(pys, HD, HD, pysh, 512, 0, 0, 2);
    k_gemmh<<<dim3(VOC/128, (TT2*NB)/128), 256>>>((const uint_t*)pysh, 256,
        (const uint_t*)poWh, 256, out_b, dout, VOC, 512);

    // final hidden states
    k_fin<<<(2*BHD + 255)/256, 256>>>(dout);
    (void)in_sizes; (void)n_in; (void)out_size;
}

// round 12
// speedup vs baseline: 1.3114x; 1.0380x over previous
#include <cuda_runtime.h>
#include <cuda_fp16.h>
#include <cstddef>
#include <cstdint>

#define HD   512
#define VOC  32000
#define TT1  128
#define TT2  64
#define NB   32
#define H3   1536
#define BHD  (NB*HD)
#define YSZ  ((size_t)TT2*NB*VOC)
#define HF_OFF YSZ
#define LS_OFF (YSZ + (size_t)2*BHD)

typedef unsigned int uint_t;

// ---------------- scratch (device globals; no runtime alloc) ----------------
__device__ float g_X  [TT2*NB*HD];
__device__ float g_q  [TT2*NB*HD];
__device__ float g_ep [TT1*NB*HD];
__device__ float g_sc [TT2*TT1*NB];
__device__ float g_av [TT2*NB*HD];
__device__ float g_gi0[TT2*NB*H3];
__device__ float g_ys [TT2*NB*HD];
__device__ float g_h0c[2*BHD];
__device__ float g_h1c[2*BHD];

// fp16 operands
__device__ __align__(16) __half h_ench [(size_t)TT1*NB * 1024];  // A2: [hi|lo]
__device__ __align__(16) __half h_Wxh  [512 * 1024];             // B2: [hi|hi]
__device__ __align__(16) __half h_Weh  [512 * 1024];             // B2
__device__ __align__(16) __half h_Xh   [(size_t)TT2*NB * 1024];  // A2
__device__ __align__(16) __half h_Xavh [(size_t)TT2*NB * 2048];  // A2 of [X|av]
__device__ __align__(16) __half h_Wih0h[(size_t)H3 * 2048];      // B2
__device__ __align__(16) __half h_oWh  [(size_t)VOC * 512];      // 1-term
__device__ __align__(16) __half h_ysh  [(size_t)TT2*NB * 512];   // 1-term

// grid barrier state (monotonic; reset by k_embed each launch)
__device__ unsigned g_bcnt = 0;

__device__ __forceinline__ int CH(int b, int k){ return ((k>>2)<<7) + (b<<2) + (k&3); }

__device__ __forceinline__ float fast_tanh(float x){
    float e = __expf(2.f*x);
    return 1.f - __fdividef(2.f, e + 1.f);
}
__device__ __forceinline__ float fast_sig(float x){
    return __fdividef(1.f, 1.f + __expf(-x));
}

// ---------------- embed + state init + barrier reset ----------------
__global__ __launch_bounds__(256) void k_embed(const int* __restrict__ tok,
                                               const float* __restrict__ emb,
                                               const float* __restrict__ state)
{
    int i = blockIdx.x*256 + threadIdx.x;
    if (i == 0) g_bcnt = 0;
    if (i < TT2*NB*HD){
        int row = i >> 9;
        int h   = i & (HD-1);
        g_X[i] = emb[(size_t)tok[row]*HD + h];
    }
    if (i < 2*BHD){
        int l = (i >= BHD);
        int r = i & (BHD-1);
        int b = r >> 9, h = r & (HD-1);
        float v = state[i];
        if (l == 0) g_h0c[CH(b,h)] = v;
        else        g_h1c[CH(b,h)] = v;
    }
}

// ---------------- fp32 -> fp16 split conversion ----------------
__device__ __forceinline__ uint_t packh(__half a, __half b){
    return ((uint_t)__half_as_ushort(b) << 16) | (uint_t)__half_as_ushort(a);
}
__global__ void k_cath(const float* __restrict__ src, int src_ld, int Ksrc,
                       __half* __restrict__ dst, int dst_ld,
                       int off0, int off1, int mode)
{
    int row = blockIdx.x;
    for (int k = threadIdx.x*4; k < Ksrc; k += blockDim.x*4){
        float4 v = *reinterpret_cast<const float4*>(src + (size_t)row*src_ld + k);
        __half h0 = __float2half_rn(v.x), h1 = __float2half_rn(v.y);
        __half h2 = __float2half_rn(v.z), h3 = __float2half_rn(v.w);
        uint2 hv = make_uint2(packh(h0,h1), packh(h2,h3));
        *reinterpret_cast<uint2*>(dst + (size_t)row*dst_ld + off0 + k) = hv;
        if (mode == 0){
            __half l0 = __float2half_rn(v.x - __half2float(h0));
            __half l1 = __float2half_rn(v.y - __half2float(h1));
            __half l2 = __float2half_rn(v.z - __half2float(h2));
            __half l3 = __float2half_rn(v.w - __half2float(h3));
            uint2 lv = make_uint2(packh(l0,l1), packh(l2,l3));
            *reinterpret_cast<uint2*>(dst + (size_t)row*dst_ld + off1 + k) = lv;
        } else if (mode == 1){
            *reinterpret_cast<uint2*>(dst + (size_t)row*dst_ld + off1 + k) = hv;
        }
    }
}

// ---------------- fp16 GEMM: C[M,N] = A(M,K)*B(N,K)^T (+bias) ----------------
// 128x128 tile, 8 warps (2M x 4N) of 64x32. Row-major smem (stride 20 uints:
// conflict-free fragment LDS, contiguous 16B chunks) + cp.async 2-stage
// double buffer: wait_group -> sync -> issue load(c+1) -> compute(c).
__device__ __forceinline__ uint32_t s2u(const void* p){
    uint32_t a;
    asm("{ .reg .u64 t; cvta.to.shared.u64 t, %1; cvt.u32.u64 %0, t; }" : "=r"(a) : "l"(p));
    return a;
}
__device__ __forceinline__ void cpa16(uint32_t s, const void* g){
    asm volatile("cp.async.cg.shared.global [%0], [%1], 16;" :: "r"(s), "l"(g));
}
__device__ __forceinline__ void mma16f(float* d, const uint_t* a, uint_t b0, uint_t b1){
    asm volatile("mma.sync.aligned.m16n8k16.row.col.f32.f16.f16.f32 "
        "{%0,%1,%2,%3}, {%4,%5,%6,%7}, {%8,%9}, {%0,%1,%2,%3};\n"
        : "+f"(d[0]), "+f"(d[1]), "+f"(d[2]), "+f"(d[3])
        : "r"(a[0]), "r"(a[1]), "r"(a[2]), "r"(a[3]), "r"(b0), "r"(b1));
}
#define SROW 20   // uints per smem row: g*20 mod 32 all-distinct -> conflict-free

__global__ __launch_bounds__(256, 2) void k_gemmh(
    const uint_t* __restrict__ A, int lda,   // lda in uint (fp16x2) units = K/2
    const uint_t* __restrict__ B, int ldb,
    const float* __restrict__ bias,
    float* __restrict__ C, int ldc, int K)
{
    __shared__ __align__(16) uint_t sA[2][128*SROW], sB[2][128*SROW];
    const int m0 = blockIdx.y * 128;
    const int n0 = blockIdx.x * 128;
    const int tid = threadIdx.x, lane = tid & 31, warp = tid >> 5;
    const int wm = (warp & 1) * 64;
    const int wn = (warp >> 1) * 32;
    const int g  = lane >> 2, tg = lane & 3;

    const int nch = K >> 5;
    // per-thread load mapping: idx in [0,512): row = idx>>2, p = (idx&3)*4
    const int lrow = tid >> 1;                 // rows 0..127 (2 threads/row)
    const int lp   = (tid & 1) * 8;            // uint base 0 or 8

    float acc[4][4][4];
    #pragma unroll
    for (int i=0;i<4;i++)
        #pragma unroll
        for (int j=0;j<4;j++){ acc[i][j][0]=0.f; acc[i][j][1]=0.f; acc[i][j][2]=0.f; acc[i][j][3]=0.f; }

    auto load_stage = [&](int c){
        const int st  = c & 1;
        const int khu = c * 16;
        const uint_t* ga = A + (size_t)(m0 + lrow)*lda + khu + lp;
        const uint_t* gb = B + (size_t)(n0 + lrow)*ldb + khu + lp;
        uint32_t da = s2u(&sA[st][lrow*SROW + lp]);
        uint32_t db = s2u(&sB[st][lrow*SROW + lp]);
        cpa16(da,      ga);
        cpa16(da + 16, ga + 4);
        cpa16(db,      gb);
        cpa16(db + 16, gb + 4);
        asm volatile("cp.async.commit_group;" ::: "memory");
    };

    load_stage(0);
    for (int c = 0; c < nch; c++){
        asm volatile("cp.async.wait_group 0;" ::: "memory");
        __syncthreads();
        if (c + 1 < nch) load_stage(c + 1);
        const int st = c & 1;
        #pragma unroll
        for (int h2=0; h2<2; h2++){
            const int kb2 = h2*8;
            const int P0 = kb2 + tg;
            const int P1 = kb2 + tg + 4;
            #pragma unroll
            for (int mp=0; mp<2; mp++){
                uint_t ah[2][4];
                #pragma unroll
                for (int q=0;q<2;q++){
                    int r0 = wm + (mp*2+q)*16 + g;
                    ah[q][0]=sA[st][r0*SROW + P0];     ah[q][1]=sA[st][(r0+8)*SROW + P0];
                    ah[q][2]=sA[st][r0*SROW + P1];     ah[q][3]=sA[st][(r0+8)*SROW + P1];
                }
                #pragma unroll
                for (int ns=0; ns<4; ns++){
                    int col = wn + ns*8 + g;
                    uint_t b0 = sB[st][col*SROW + P0];
                    uint_t b1 = sB[st][col*SROW + P1];
                    #pragma unroll
                    for (int q=0;q<2;q++)
                        mma16f(acc[mp*2+q][ns], ah[q], b0, b1);
                }
            }
        }
        __syncthreads();
    }
    #pragma unroll
    for (int ms=0; ms<4; ms++){
        #pragma unroll
        for (int ns=0; ns<4; ns++){
            int r0  = m0 + wm + ms*16 + g;
            int col = n0 + wn + ns*8 + tg*2;
            float b0v = 0.f, b1v = 0.f;
            if (bias){ b0v = bias[col]; b1v = bias[col+1]; }
            float2 v0 = make_float2(acc[ms][ns][0]+b0v, acc[ms][ns][1]+b1v);
            float2 v1 = make_float2(acc[ms][ns][2]+b0v, acc[ms][ns][3]+b1v);
            *reinterpret_cast<float2*>(C + (size_t)r0*ldc + col)     = v0;
            *reinterpret_cast<float2*>(C + (size_t)(r0+8)*ldc + col) = v1;
        }
    }
}

// ---------------- attention logits + softmax ----------------
__global__ __launch_bounds__(256) void k_att_scores(const float* __restrict__ va,
                                                    float* __restrict__ dout)
{
    __shared__ float q8[8*HD];
    __shared__ float vsm[HD];
    __shared__ float esm[8*TT1];
    const int b   = blockIdx.y;
    const int t2b = blockIdx.x * 8;
    const int tid = threadIdx.x, lane = tid & 31, w = tid >> 5;

    for (int i = tid; i < 8*HD; i += 256){
        int t2i = i >> 9, h = i & (HD-1);
        q8[i] = g_q[((size_t)(t2b + t2i)*NB + b)*HD + h];
    }
    for (int i = tid; i < HD; i += 256) vsm[i] = va[i];
    __syncthreads();

    for (int t1 = w; t1 < TT1; t1 += 8){
        const float* ep = g_ep + ((size_t)t1*NB + b)*HD;
        float accv[8];
        #pragma unroll
        for (int i=0;i<8;i++) accv[i] = 0.f;
        for (int h = lane; h < HD; h += 32){
            float e  = ep[h];
            float vv = vsm[h];
            #pragma unroll
            for (int i=0;i<8;i++) accv[i] += vv * fast_tanh(q8[i*HD + h] + e);
        }
        #pragma unroll
        for (int i=0;i<8;i++){
            float s = accv[i];
            #pragma unroll
            for (int o=16;o;o>>=1) s += __shfl_xor_sync(0xffffffffu, s, o);
            if (lane == 0) esm[i*TT1 + t1] = s;
        }
    }
    __syncthreads();

    {
        float v[4];
        #pragma unroll
        for (int i=0;i<4;i++) v[i] = esm[w*TT1 + lane + 32*i];
        float m = fmaxf(fmaxf(v[0],v[1]), fmaxf(v[2],v[3]));
        #pragma unroll
        for (int o=16;o;o>>=1) m = fmaxf(m, __shfl_xor_sync(0xffffffffu, m, o));
        float s = 0.f;
        #pragma unroll
        for (int i=0;i<4;i++){ v[i] = __expf(v[i]-m); s += v[i]; }
        #pragma unroll
        for (int o=16;o;o>>=1) s += __shfl_xor_sync(0xffffffffu, s, o);
        float inv = __fdividef(1.f, s);
        int t2 = t2b + w;
        #pragma unroll
        for (int i=0;i<4;i++){
            int t1 = lane + 32*i;
            float sc = v[i]*inv;
            g_sc[((size_t)t2*TT1 + t1)*NB + b] = sc;
            if (t2 == TT2-1) dout[LS_OFF + (size_t)t1*NB + b] = sc;
        }
    }
}

// ---------------- attention values ----------------
__global__ __launch_bounds__(256) void k_attv(const float* __restrict__ enc)
{
    __shared__ float sst[TT1*32];
    const int b   = blockIdx.x;
    const int t2o = blockIdx.y * 32;
    const int h   = blockIdx.z * 256 + threadIdx.x;
    for (int i = threadIdx.x; i < 32*TT1; i += 256){
        int t1 = i >> 5, i2 = i & 31;
        sst[t1*32 + i2] = g_sc[((size_t)(t2o + i2)*TT1 + t1)*NB + b];
    }
    __syncthreads();
    float acc[32];
    #pragma unroll
    for (int i=0;i<32;i++) acc[i] = 0.f;
    for (int t1 = 0; t1 < TT1; t1++){
        float ev = enc[((size_t)t1*NB + b)*HD + h];
        #pragma unroll
        for (int i=0;i<32;i++) acc[i] += ev * sst[t1*32 + i];
    }
    #pragma unroll
    for (int i=0;i<32;i++)
        g_av[((size_t)(t2o+i)*NB + b)*HD + h] = acc[i];
}

// ---------------- persistent recurrence (smem-staged, unchanged R11) --------
#define NBLK 192

__device__ __forceinline__ void dotsm(const float* __restrict__ W, int j,
                                      const float* __restrict__ shb, int b,
                                      int kb, int kn,
                                      float& s0, float& s1, float& s2)
{
    const float* w0 = W + (size_t) j        *HD + kb;
    const float* w1 = W + (size_t)(j+ 512)  *HD + kb;
    const float* w2 = W + (size_t)(j+1024)  *HD + kb;
    float a0=s0, a1=s1, a2=s2;
    #pragma unroll 8
    for (int kk = 0; kk < kn; kk += 4){
        float4 hv = *reinterpret_cast<const float4*>(shb + ((kk>>2)<<7) + (b<<2));
        float4 x = *reinterpret_cast<const float4*>(w0 + kk);
        float4 y = *reinterpret_cast<const float4*>(w1 + kk);
        float4 z = *reinterpret_cast<const float4*>(w2 + kk);
        a0 += x.x*hv.x + x.y*hv.y + x.z*hv.z + x.w*hv.w;
        a1 += y.x*hv.x + y.y*hv.y + y.z*hv.z + y.w*hv.w;
        a2 += z.x*hv.x + z.y*hv.y + z.z*hv.z + z.w*hv.w;
    }
    s0 = a0; s1 = a1; s2 = a2;
}

__global__ __launch_bounds__(256, 2) void k_rec(
    const float* __restrict__ W_hh0, const float* __restrict__ b_hh0,
    const float* __restrict__ W_ih1, const float* __restrict__ b_ih1,
    const float* __restrict__ W_hh1, const float* __restrict__ b_hh1)
{
    extern __shared__ float sh[];
    __shared__ float sm[8][3][32];
    const int blk  = blockIdx.x;
    const int tid  = threadIdx.x;
    const int warp = tid >> 5;
    const int b    = tid & 31;

    for (int t = 0; t <= TT2; t++){
        if (blk < 64){
            if (t < TT2){
                const float* sp = g_h0c + (t&1)*BHD;
                #pragma unroll
                for (int i = tid*4; i < BHD; i += 1024)
                    *reinterpret_cast<float4*>(sh + i) =
                        __ldcg(reinterpret_cast<const float4*>(sp + i));
                __syncthreads();
                const int j = blk*8 + warp;
                float s0=0.f, s1=0.f, s2=0.f;
                dotsm(W_hh0, j, sh, b, 0, HD, s0, s1, s2);
                const float* gi = g_gi0 + ((size_t)t*NB + b)*H3;
                float r = fast_sig (gi[j      ] + s0 + b_hh0[j      ]);
                float z = fast_sig (gi[j+ 512] + s1 + b_hh0[j+ 512]);
                float n = fast_tanh(gi[j+1024] + r*(s2 + b_hh0[j+1024]));
                float hold = sh[CH(b,j)];
                __stcg(&g_h0c[(1-(t&1))*BHD + CH(b,j)], (1.f-z)*n + z*hold);
            }
        } else {
            if (t >= 1){
                const int s    = t - 1;
                const int blk2 = blk - 64;
                const int j    = blk2*4 + (warp >> 1);
                const int mat  = warp & 1;
                const int p1   = s & 1;
                const float* W = (mat == 0) ? W_ih1 : W_hh1;
                float s0=0.f, s1=0.f, s2=0.f;
                #pragma unroll
                for (int ph = 0; ph < 2; ph++){
                    const float* h0src = g_h0c + (t&1)*BHD + ph*8192;
                    const float* h1src = g_h1c + p1  *BHD + ph*8192;
                    #pragma unroll
                    for (int i = tid*4; i < 8192; i += 1024){
                        *reinterpret_cast<float4*>(sh + i) =
                            __ldcg(reinterpret_cast<const float4*>(h0src + i));
                        *reinterpret_cast<float4*>(sh + 8192 + i) =
                            __ldcg(reinterpret_cast<const float4*>(h1src + i));
                    }
                    __syncthreads();
                    dotsm(W, j, sh + mat*8192, b, ph*256, 256, s0, s1, s2);
                    __syncthreads();
                }
                sm[warp][0][b] = s0; sm[warp][1][b] = s1; sm[warp][2][b] = s2;
                __syncthreads();
                if (mat == 0){
                    float xr = s0 + b_ih1[j      ];
                    float xz = s1 + b_ih1[j+ 512];
                    float xn = s2 + b_ih1[j+1024];
                    float hr = sm[warp+1][0][b] + b_hh1[j      ];
                    float hz = sm[warp+1][1][b] + b_hh1[j+ 512];
                    float hn = sm[warp+1][2][b] + b_hh1[j+1024];
                    float r = fast_sig(xr + hr);
                    float z = fast_sig(xz + hz);
                    float n = fast_tanh(xn + r*hn);
                    float h1old = __ldcg(&g_h1c[p1*BHD + CH(b,j)]);
                    float hnew = (1.f-z)*n + z*h1old;
                    __stcg(&g_h1c[((s+1)&1)*BHD + CH(b,j)], hnew);
                    g_ys[((size_t)s*NB + b)*HD + j] = hnew;
                }
            }
        }
        if (t == TT2) break;
        __syncthreads();
        if (tid == 0){
            __threadfence();
            atomicAdd(&g_bcnt, 1u);
            unsigned tgt = (unsigned)(t + 1) * NBLK;
            while (__ldcg(&g_bcnt) < tgt) __nanosleep(64);
            __threadfence();
        }
        __syncthreads();
    }
}

// ---------------- final state copy ----------------
__global__ __launch_bounds__(256) void k_fin(float* __restrict__ dout)
{
    int i = blockIdx.x*256 + threadIdx.x;
    if (i >= 2*BHD) return;
    int l = (i >= BHD);
    int r = i & (BHD-1);
    int b = r >> 9, h = r & (HD-1);
    float v = l ? g_h1c[CH(b,h)] : g_h0c[CH(b,h)];
    dout[HF_OFF + i] = v;
}

extern "C" void kernel_launch(void* const* d_in, const int* in_sizes, int n_in,
                              void* d_out, int out_size)
{
    const int*   tok   = (const int*)  d_in[0];
    const float* state = (const float*)d_in[1];
    const float* enc   = (const float*)d_in[2];
    const float* emb   = (const float*)d_in[3];
    const float* wa_W  = (const float*)d_in[4];
    const float* wa_b  = (const float*)d_in[5];
    const float* va_W  = (const float*)d_in[6];
    const float* W_ih0 = (const float*)d_in[7];
    const float* W_hh0 = (const float*)d_in[8];
    const float* b_ih0 = (const float*)d_in[9];
    const float* b_hh0 = (const float*)d_in[10];
    const float* W_ih1 = (const float*)d_in[11];
    const float* W_hh1 = (const float*)d_in[12];
    const float* b_ih1 = (const float*)d_in[13];
    const float* b_hh1 = (const float*)d_in[14];
    const float* out_W = (const float*)d_in[15];
    const float* out_b = (const float*)d_in[16];
    float* dout = (float*)d_out;

    float *pX, *pep, *pq, *pav, *pgi0, *pys;
    __half *pench, *pWxh, *pWeh, *pXh, *pXavh, *pWih0h, *poWh, *pysh;
    cudaGetSymbolAddress((void**)&pX,     g_X);
    cudaGetSymbolAddress((void**)&pep,    g_ep);
    cudaGetSymbolAddress((void**)&pq,     g_q);
    cudaGetSymbolAddress((void**)&pav,    g_av);
    cudaGetSymbolAddress((void**)&pgi0,   g_gi0);
    cudaGetSymbolAddress((void**)&pys,    g_ys);
    cudaGetSymbolAddress((void**)&pench,  h_ench);
    cudaGetSymbolAddress((void**)&pWxh,   h_Wxh);
    cudaGetSymbolAddress((void**)&pWeh,   h_Weh);
    cudaGetSymbolAddress((void**)&pXh,    h_Xh);
    cudaGetSymbolAddress((void**)&pXavh,  h_Xavh);
    cudaGetSymbolAddress((void**)&pWih0h, h_Wih0h);
    cudaGetSymbolAddress((void**)&poWh,   h_oWh);
    cudaGetSymbolAddress((void**)&pysh,   h_ysh);

    cudaFuncSetAttribute(k_rec, cudaFuncAttributeMaxDynamicSharedMemorySize, 65536);

    // --- launch order: my launch #4 is the enc_proj GEMM (ncu lands there) ---
    // 1. embed + state init + barrier reset
    k_embed<<<(TT2*NB*HD + 255)/256, 256>>>(tok, emb, state);
    // 2-3. conversions needed by enc_proj
    k_cath<<<TT1*NB, 128>>>(enc,        HD, HD, pench, 1024, 0, 512, 0);   // A2
    k_cath<<<512,    128>>>(wa_W + HD, 2*HD, HD, pWeh, 1024, 0, 512, 1);   // B2
    // 4. enc_proj = enc @ We^T + wa_b   (M=4096, N=512, K'=1024)  << profiled
    k_gemmh<<<dim3(HD/128, (TT1*NB)/128), 256>>>((const uint_t*)pench, 512,
        (const uint_t*)pWeh, 512, wa_b, pep, HD, 1024);
    // 5-6. conversions for q
    k_cath<<<512,    128>>>(wa_W,      2*HD, HD, pWxh, 1024, 0, 512, 1);   // B2
    k_cath<<<TT2*NB, 128>>>(pX,         HD, HD, pXh,  1024, 0, 512, 0);    // A2
    // 7. q = X @ Wx^T                   (M=2048, N=512, K'=1024)
    k_gemmh<<<dim3(HD/128, (TT2*NB)/128), 256>>>((const uint_t*)pXh, 512,
        (const uint_t*)pWxh, 512, nullptr, pq, HD, 1024);

    // remaining conversions
    k_cath<<<H3,     256>>>(W_ih0, 2*HD, 2*HD, pWih0h, 2048, 0, 1024, 1);  // B2
    k_cath<<<VOC,    128>>>(out_W,   HD,   HD, poWh,    512, 0, 0, 2);     // 1-term
    k_cath<<<TT2*NB, 128>>>(pX,      HD,   HD, pXavh,  2048, 0, 1024, 0);  // A2 (X part)

    // attention
    k_att_scores<<<dim3(TT2/8, NB), 256>>>(va_W, dout);
    k_attv<<<dim3(NB, TT2/32, HD/256), 256>>>(enc);
    k_cath<<<TT2*NB, 128>>>(pav, HD, HD, pXavh, 2048, 512, 1536, 0);       // A2 (av part)

    // gi0 = [X, att_v] @ W_ih0^T + b_ih0   (M=2048, N=1536, K'=2048)
    k_gemmh<<<dim3(H3/128, (TT2*NB)/128), 256>>>((const uint_t*)pXavh, 1024,
        (const uint_t*)pWih0h, 1024, b_ih0, pgi0, H3, 2048);

    // recurrence (64KB dynamic smem per block)
    k_rec<<<NBLK, 256, 65536>>>(W_hh0, b_hh0, W_ih1, b_ih1, W_hh1, b_hh1);

    // y = ys @ out_W^T + out_b   (M=2048, N=32000, K=512, 1-term fp16)
    k_cath<<<TT2*NB, 128>>>(pys, HD, HD, pysh, 512, 0, 0, 2);
    k_gemmh<<<dim3(VOC/128, (TT2*NB)/128), 256>>>((const uint_t*)pysh, 256,
        (const uint_t*)poWh, 256, out_b, dout, VOC, 512);

    // final hidden states
    k_fin<<<(2*BHD + 255)/256, 256>>>(dout);
    (void)in_sizes; (void)n_in; (void)out_size;
}

// round 13
// speedup vs baseline: 1.3235x; 1.0093x over previous
#include <cuda_runtime.h>
#include <cuda_fp16.h>
#include <cstddef>
#include <cstdint>

#define HD   512
#define VOC  32000
#define TT1  128
#define TT2  64
#define NB   32
#define H3   1536
#define BHD  (NB*HD)
#define YSZ  ((size_t)TT2*NB*VOC)
#define HF_OFF YSZ
#define LS_OFF (YSZ + (size_t)2*BHD)

typedef unsigned int uint_t;

// ---------------- scratch (device globals; no runtime alloc) ----------------
__device__ float g_X  [TT2*NB*HD];
__device__ float g_q  [TT2*NB*HD];
__device__ float g_ep [TT1*NB*HD];
__device__ float g_sc [TT2*TT1*NB];
__device__ float g_av [TT2*NB*HD];
__device__ float g_gi0[TT2*NB*H3];
__device__ float g_ys [TT2*NB*HD];
__device__ float g_h0c[2*BHD];
__device__ float g_h1c[2*BHD];

// fp16 operands
__device__ __align__(16) __half h_ench [(size_t)TT1*NB * 1024];  // A2: [hi|lo]
__device__ __align__(16) __half h_Wxh  [512 * 1024];             // B2: [hi|hi]
__device__ __align__(16) __half h_Weh  [512 * 1024];             // B2
__device__ __align__(16) __half h_Xh   [(size_t)TT2*NB * 1024];  // A2
__device__ __align__(16) __half h_Xavh [(size_t)TT2*NB * 2048];  // A2 of [X|av]
__device__ __align__(16) __half h_Wih0h[(size_t)H3 * 2048];      // B2
__device__ __align__(16) __half h_oWh  [(size_t)VOC * 512];      // 1-term
__device__ __align__(16) __half h_ysh  [(size_t)TT2*NB * 512];   // 1-term

// grid barrier state (monotonic; reset by k_embed each launch)
__device__ unsigned g_bcnt = 0;

__device__ __forceinline__ int CH(int b, int k){ return ((k>>2)<<7) + (b<<2) + (k&3); }

__device__ __forceinline__ float fast_tanh(float x){
    float e = __expf(2.f*x);
    return 1.f - __fdividef(2.f, e + 1.f);
}
__device__ __forceinline__ float fast_sig(float x){
    return __fdividef(1.f, 1.f + __expf(-x));
}

// ---------------- embed + state init + barrier reset ----------------
__global__ __launch_bounds__(256) void k_embed(const int* __restrict__ tok,
                                               const float* __restrict__ emb,
                                               const float* __restrict__ state)
{
    int i = blockIdx.x*256 + threadIdx.x;
    if (i == 0) g_bcnt = 0;
    if (i < TT2*NB*HD){
        int row = i >> 9;
        int h   = i & (HD-1);
        g_X[i] = emb[(size_t)tok[row]*HD + h];
    }
    if (i < 2*BHD){
        int l = (i >= BHD);
        int r = i & (BHD-1);
        int b = r >> 9, h = r & (HD-1);
        float v = state[i];
        if (l == 0) g_h0c[CH(b,h)] = v;
        else        g_h1c[CH(b,h)] = v;
    }
}

// ---------------- fp32 -> fp16 split conversion ----------------
__device__ __forceinline__ uint_t packh(__half a, __half b){
    return ((uint_t)__half_as_ushort(b) << 16) | (uint_t)__half_as_ushort(a);
}
__global__ void k_cath(const float* __restrict__ src, int src_ld, int Ksrc,
                       __half* __restrict__ dst, int dst_ld,
                       int off0, int off1, int mode)
{
    int row = blockIdx.x;
    for (int k = threadIdx.x*4; k < Ksrc; k += blockDim.x*4){
        float4 v = *reinterpret_cast<const float4*>(src + (size_t)row*src_ld + k);
        __half h0 = __float2half_rn(v.x), h1 = __float2half_rn(v.y);
        __half h2 = __float2half_rn(v.z), h3 = __float2half_rn(v.w);
        uint2 hv = make_uint2(packh(h0,h1), packh(h2,h3));
        *reinterpret_cast<uint2*>(dst + (size_t)row*dst_ld + off0 + k) = hv;
        if (mode == 0){
            __half l0 = __float2half_rn(v.x - __half2float(h0));
            __half l1 = __float2half_rn(v.y - __half2float(h1));
            __half l2 = __float2half_rn(v.z - __half2float(h2));
            __half l3 = __float2half_rn(v.w - __half2float(h3));
            uint2 lv = make_uint2(packh(l0,l1), packh(l2,l3));
            *reinterpret_cast<uint2*>(dst + (size_t)row*dst_ld + off1 + k) = lv;
        } else if (mode == 1){
            *reinterpret_cast<uint2*>(dst + (size_t)row*dst_ld + off1 + k) = hv;
        }
    }
}

// ---------------- fp16 GEMM (R12: cp.async 2-stage, stride-20 smem) ---------
__device__ __forceinline__ uint32_t s2u(const void* p){
    uint32_t a;
    asm("{ .reg .u64 t; cvta.to.shared.u64 t, %1; cvt.u32.u64 %0, t; }" : "=r"(a) : "l"(p));
    return a;
}
__device__ __forceinline__ void cpa16(uint32_t s, const void* g){
    asm volatile("cp.async.cg.shared.global [%0], [%1], 16;" :: "r"(s), "l"(g));
}
__device__ __forceinline__ void mma16f(float* d, const uint_t* a, uint_t b0, uint_t b1){
    asm volatile("mma.sync.aligned.m16n8k16.row.col.f32.f16.f16.f32 "
        "{%0,%1,%2,%3}, {%4,%5,%6,%7}, {%8,%9}, {%0,%1,%2,%3};\n"
        : "+f"(d[0]), "+f"(d[1]), "+f"(d[2]), "+f"(d[3])
        : "r"(a[0]), "r"(a[1]), "r"(a[2]), "r"(a[3]), "r"(b0), "r"(b1));
}
#define SROW 20

__global__ __launch_bounds__(256, 2) void k_gemmh(
    const uint_t* __restrict__ A, int lda,
    const uint_t* __restrict__ B, int ldb,
    const float* __restrict__ bias,
    float* __restrict__ C, int ldc, int K)
{
    __shared__ __align__(16) uint_t sA[2][128*SROW], sB[2][128*SROW];
    const int m0 = blockIdx.y * 128;
    const int n0 = blockIdx.x * 128;
    const int tid = threadIdx.x, lane = tid & 31, warp = tid >> 5;
    const int wm = (warp & 1) * 64;
    const int wn = (warp >> 1) * 32;
    const int g  = lane >> 2, tg = lane & 3;

    const int nch = K >> 5;
    const int lrow = tid >> 1;
    const int lp   = (tid & 1) * 8;

    float acc[4][4][4];
    #pragma unroll
    for (int i=0;i<4;i++)
        #pragma unroll
        for (int j=0;j<4;j++){ acc[i][j][0]=0.f; acc[i][j][1]=0.f; acc[i][j][2]=0.f; acc[i][j][3]=0.f; }

    auto load_stage = [&](int c){
        const int st  = c & 1;
        const int khu = c * 16;
        const uint_t* ga = A + (size_t)(m0 + lrow)*lda + khu + lp;
        const uint_t* gb = B + (size_t)(n0 + lrow)*ldb + khu + lp;
        uint32_t da = s2u(&sA[st][lrow*SROW + lp]);
        uint32_t db = s2u(&sB[st][lrow*SROW + lp]);
        cpa16(da,      ga);
        cpa16(da + 16, ga + 4);
        cpa16(db,      gb);
        cpa16(db + 16, gb + 4);
        asm volatile("cp.async.commit_group;" ::: "memory");
    };

    load_stage(0);
    for (int c = 0; c < nch; c++){
        asm volatile("cp.async.wait_group 0;" ::: "memory");
        __syncthreads();
        if (c + 1 < nch) load_stage(c + 1);
        const int st = c & 1;
        #pragma unroll
        for (int h2=0; h2<2; h2++){
            const int kb2 = h2*8;
            const int P0 = kb2 + tg;
            const int P1 = kb2 + tg + 4;
            #pragma unroll
            for (int mp=0; mp<2; mp++){
                uint_t ah[2][4];
                #pragma unroll
                for (int q=0;q<2;q++){
                    int r0 = wm + (mp*2+q)*16 + g;
                    ah[q][0]=sA[st][r0*SROW + P0];     ah[q][1]=sA[st][(r0+8)*SROW + P0];
                    ah[q][2]=sA[st][r0*SROW + P1];     ah[q][3]=sA[st][(r0+8)*SROW + P1];
                }
                #pragma unroll
                for (int ns=0; ns<4; ns++){
                    int col = wn + ns*8 + g;
                    uint_t b0 = sB[st][col*SROW + P0];
                    uint_t b1 = sB[st][col*SROW + P1];
                    #pragma unroll
                    for (int q=0;q<2;q++)
                        mma16f(acc[mp*2+q][ns], ah[q], b0, b1);
                }
            }
        }
        __syncthreads();
    }
    #pragma unroll
    for (int ms=0; ms<4; ms++){
        #pragma unroll
        for (int ns=0; ns<4; ns++){
            int r0  = m0 + wm + ms*16 + g;
            int col = n0 + wn + ns*8 + tg*2;
            float b0v = 0.f, b1v = 0.f;
            if (bias){ b0v = bias[col]; b1v = bias[col+1]; }
            float2 v0 = make_float2(acc[ms][ns][0]+b0v, acc[ms][ns][1]+b1v);
            float2 v1 = make_float2(acc[ms][ns][2]+b0v, acc[ms][ns][3]+b1v);
            *reinterpret_cast<float2*>(C + (size_t)r0*ldc + col)     = v0;
            *reinterpret_cast<float2*>(C + (size_t)(r0+8)*ldc + col) = v1;
        }
    }
}

// ---------------- attention logits + softmax ----------------
__global__ __launch_bounds__(256) void k_att_scores(const float* __restrict__ va,
                                                    float* __restrict__ dout)
{
    __shared__ float q8[8*HD];
    __shared__ float vsm[HD];
    __shared__ float esm[8*TT1];
    const int b   = blockIdx.y;
    const int t2b = blockIdx.x * 8;
    const int tid = threadIdx.x, lane = tid & 31, w = tid >> 5;

    for (int i = tid; i < 8*HD; i += 256){
        int t2i = i >> 9, h = i & (HD-1);
        q8[i] = g_q[((size_t)(t2b + t2i)*NB + b)*HD + h];
    }
    for (int i = tid; i < HD; i += 256) vsm[i] = va[i];
    __syncthreads();

    for (int t1 = w; t1 < TT1; t1 += 8){
        const float* ep = g_ep + ((size_t)t1*NB + b)*HD;
        float accv[8];
        #pragma unroll
        for (int i=0;i<8;i++) accv[i] = 0.f;
        for (int h = lane; h < HD; h += 32){
            float e  = ep[h];
            float vv = vsm[h];
            #pragma unroll
            for (int i=0;i<8;i++) accv[i] += vv * fast_tanh(q8[i*HD + h] + e);
        }
        #pragma unroll
        for (int i=0;i<8;i++){
            float s = accv[i];
            #pragma unroll
            for (int o=16;o;o>>=1) s += __shfl_xor_sync(0xffffffffu, s, o);
            if (lane == 0) esm[i*TT1 + t1] = s;
        }
    }
    __syncthreads();

    {
        float v[4];
        #pragma unroll
        for (int i=0;i<4;i++) v[i] = esm[w*TT1 + lane + 32*i];
        float m = fmaxf(fmaxf(v[0],v[1]), fmaxf(v[2],v[3]));
        #pragma unroll
        for (int o=16;o;o>>=1) m = fmaxf(m, __shfl_xor_sync(0xffffffffu, m, o));
        float s = 0.f;
        #pragma unroll
        for (int i=0;i<4;i++){ v[i] = __expf(v[i]-m); s += v[i]; }
        #pragma unroll
        for (int o=16;o;o>>=1) s += __shfl_xor_sync(0xffffffffu, s, o);
        float inv = __fdividef(1.f, s);
        int t2 = t2b + w;
        #pragma unroll
        for (int i=0;i<4;i++){
            int t1 = lane + 32*i;
            float sc = v[i]*inv;
            g_sc[((size_t)t2*TT1 + t1)*NB + b] = sc;
            if (t2 == TT2-1) dout[LS_OFF + (size_t)t1*NB + b] = sc;
        }
    }
}

// ---------------- attention values ----------------
__global__ __launch_bounds__(256) void k_attv(const float* __restrict__ enc)
{
    __shared__ float sst[TT1*32];
    const int b   = blockIdx.x;
    const int t2o = blockIdx.y * 32;
    const int h   = blockIdx.z * 256 + threadIdx.x;
    for (int i = threadIdx.x; i < 32*TT1; i += 256){
        int t1 = i >> 5, i2 = i & 31;
        sst[t1*32 + i2] = g_sc[((size_t)(t2o + i2)*TT1 + t1)*NB + b];
    }
    __syncthreads();
    float acc[32];
    #pragma unroll
    for (int i=0;i<32;i++) acc[i] = 0.f;
    for (int t1 = 0; t1 < TT1; t1++){
        float ev = enc[((size_t)t1*NB + b)*HD + h];
        #pragma unroll
        for (int i=0;i<32;i++) acc[i] += ev * sst[t1*32 + i];
    }
    #pragma unroll
    for (int i=0;i<32;i++)
        g_av[((size_t)(t2o+i)*NB + b)*HD + h] = acc[i];
}

// ---------------- persistent recurrence: release/acquire barrier (NO L1 flush)
#define NBLK 192

__device__ __forceinline__ void dotsm(const float* __restrict__ W, int j,
                                      const float* __restrict__ shb, int b,
                                      int kb, int kn,
                                      float& s0, float& s1, float& s2)
{
    const float* w0 = W + (size_t) j        *HD + kb;
    const float* w1 = W + (size_t)(j+ 512)  *HD + kb;
    const float* w2 = W + (size_t)(j+1024)  *HD + kb;
    float a0=s0, a1=s1, a2=s2;
    #pragma unroll 8
    for (int kk = 0; kk < kn; kk += 4){
        float4 hv = *reinterpret_cast<const float4*>(shb + ((kk>>2)<<7) + (b<<2));
        float4 x = *reinterpret_cast<const float4*>(w0 + kk);
        float4 y = *reinterpret_cast<const float4*>(w1 + kk);
        float4 z = *reinterpret_cast<const float4*>(w2 + kk);
        a0 += x.x*hv.x + x.y*hv.y + x.z*hv.z + x.w*hv.w;
        a1 += y.x*hv.x + y.y*hv.y + y.z*hv.z + y.w*hv.w;
        a2 += z.x*hv.x + z.y*hv.y + z.z*hv.z + z.w*hv.w;
    }
    s0 = a0; s1 = a1; s2 = a2;
}

__global__ __launch_bounds__(256, 2) void k_rec(
    const float* __restrict__ W_hh0, const float* __restrict__ b_hh0,
    const float* __restrict__ W_ih1, const float* __restrict__ b_ih1,
    const float* __restrict__ W_hh1, const float* __restrict__ b_hh1)
{
    extern __shared__ float sh[];
    __shared__ float sm[8][3][32];
    const int blk  = blockIdx.x;
    const int tid  = threadIdx.x;
    const int warp = tid >> 5;
    const int b    = tid & 31;

    for (int t = 0; t <= TT2; t++){
        if (blk < 64){
            if (t < TT2){
                const float* sp = g_h0c + (t&1)*BHD;
                #pragma unroll
                for (int i = tid*4; i < BHD; i += 1024)
                    *reinterpret_cast<float4*>(sh + i) =
                        __ldcg(reinterpret_cast<const float4*>(sp + i));
                __syncthreads();
                const int j = blk*8 + warp;
                float s0=0.f, s1=0.f, s2=0.f;
                dotsm(W_hh0, j, sh, b, 0, HD, s0, s1, s2);
                const float* gi = g_gi0 + ((size_t)t*NB + b)*H3;
                float r = fast_sig (gi[j      ] + s0 + b_hh0[j      ]);
                float z = fast_sig (gi[j+ 512] + s1 + b_hh0[j+ 512]);
                float n = fast_tanh(gi[j+1024] + r*(s2 + b_hh0[j+1024]));
                float hold = sh[CH(b,j)];
                __stcg(&g_h0c[(1-(t&1))*BHD + CH(b,j)], (1.f-z)*n + z*hold);
            }
        } else {
            if (t >= 1){
                const int s    = t - 1;
                const int blk2 = blk - 64;
                const int j    = blk2*4 + (warp >> 1);
                const int mat  = warp & 1;
                const int p1   = s & 1;
                const float* W = (mat == 0) ? W_ih1 : W_hh1;
                float s0=0.f, s1=0.f, s2=0.f;
                #pragma unroll
                for (int ph = 0; ph < 2; ph++){
                    const float* h0src = g_h0c + (t&1)*BHD + ph*8192;
                    const float* h1src = g_h1c + p1  *BHD + ph*8192;
                    #pragma unroll
                    for (int i = tid*4; i < 8192; i += 1024){
                        *reinterpret_cast<float4*>(sh + i) =
                            __ldcg(reinterpret_cast<const float4*>(h0src + i));
                        *reinterpret_cast<float4*>(sh + 8192 + i) =
                            __ldcg(reinterpret_cast<const float4*>(h1src + i));
                    }
                    __syncthreads();
                    dotsm(W, j, sh + mat*8192, b, ph*256, 256, s0, s1, s2);
                    __syncthreads();
                }
                sm[warp][0][b] = s0; sm[warp][1][b] = s1; sm[warp][2][b] = s2;
                __syncthreads();
                if (mat == 0){
                    float xr = s0 + b_ih1[j      ];
                    float xz = s1 + b_ih1[j+ 512];
                    float xn = s2 + b_ih1[j+1024];
                    float hr = sm[warp+1][0][b] + b_hh1[j      ];
                    float hz = sm[warp+1][1][b] + b_hh1[j+ 512];
                    float hn = sm[warp+1][2][b] + b_hh1[j+1024];
                    float r = fast_sig(xr + hr);
                    float z = fast_sig(xz + hz);
                    float n = fast_tanh(xn + r*hn);
                    float h1old = __ldcg(&g_h1c[p1*BHD + CH(b,j)]);
                    float hnew = (1.f-z)*n + z*h1old;
                    __stcg(&g_h1c[((s+1)&1)*BHD + CH(b,j)], hnew);
                    g_ys[((size_t)s*NB + b)*HD + j] = hnew;
                }
            }
        }
        if (t == TT2) break;
        // ---- grid barrier: release-add + acquire-poll. NO __threadfence
        //      (threadfence = CCTL.IVALL would flush the L1-resident weights).
        //      h state moves via __stcg/__ldcg (L2-coherent), so release/acquire
        //      on the counter is the full ordering requirement.
        __syncthreads();
        if (tid == 0){
            unsigned old, cur;
            asm volatile("atom.release.gpu.global.add.u32 %0, [%1], %2;"
                         : "=r"(old) : "l"(&g_bcnt), "r"(1u) : "memory");
            const unsigned tgt = (unsigned)(t + 1) * NBLK;
            do {
                asm volatile("ld.acquire.gpu.global.u32 %0, [%1];"
                             : "=r"(cur) : "l"(&g_bcnt) : "memory");
                if (cur < tgt) __nanosleep(32);
            } while (cur < tgt);
        }
        __syncthreads();
    }
}

// ---------------- final state copy ----------------
__global__ __launch_bounds__(256) void k_fin(float* __restrict__ dout)
{
    int i = blockIdx.x*256 + threadIdx.x;
    if (i >= 2*BHD) return;
    int l = (i >= BHD);
    int r = i & (BHD-1);
    int b = r >> 9, h = r & (HD-1);
    float v = l ? g_h1c[CH(b,h)] : g_h0c[CH(b,h)];
    dout[HF_OFF + i] = v;
}

extern "C" void kernel_launch(void* const* d_in, const int* in_sizes, int n_in,
                              void* d_out, int out_size)
{
    const int*   tok   = (const int*)  d_in[0];
    const float* state = (const float*)d_in[1];
    const float* enc   = (const float*)d_in[2];
    const float* emb   = (const float*)d_in[3];
    const float* wa_W  = (const float*)d_in[4];
    const float* wa_b  = (const float*)d_in[5];
    const float* va_W  = (const float*)d_in[6];
    const float* W_ih0 = (const float*)d_in[7];
    const float* W_hh0 = (const float*)d_in[8];
    const float* b_ih0 = (const float*)d_in[9];
    const float* b_hh0 = (const float*)d_in[10];
    const float* W_ih1 = (const float*)d_in[11];
    const float* W_hh1 = (const float*)d_in[12];
    const float* b_ih1 = (const float*)d_in[13];
    const float* b_hh1 = (const float*)d_in[14];
    const float* out_W = (const float*)d_in[15];
    const float* out_b = (const float*)d_in[16];
    float* dout = (float*)d_out;

    float *pX, *pep, *pq, *pav, *pgi0, *pys;
    __half *pench, *pWxh, *pWeh, *pXh, *pXavh, *pWih0h, *poWh, *pysh;
    cudaGetSymbolAddress((void**)&pX,     g_X);
    cudaGetSymbolAddress((void**)&pep,    g_ep);
    cudaGetSymbolAddress((void**)&pq,     g_q);
    cudaGetSymbolAddress((void**)&pav,    g_av);
    cudaGetSymbolAddress((void**)&pgi0,   g_gi0);
    cudaGetSymbolAddress((void**)&pys,    g_ys);
    cudaGetSymbolAddress((void**)&pench,  h_ench);
    cudaGetSymbolAddress((void**)&pWxh,   h_Wxh);
    cudaGetSymbolAddress((void**)&pWeh,   h_Weh);
    cudaGetSymbolAddress((void**)&pXh,    h_Xh);
    cudaGetSymbolAddress((void**)&pXavh,  h_Xavh);
    cudaGetSymbolAddress((void**)&pWih0h, h_Wih0h);
    cudaGetSymbolAddress((void**)&poWh,   h_oWh);
    cudaGetSymbolAddress((void**)&pysh,   h_ysh);

    cudaFuncSetAttribute(k_rec, cudaFuncAttributeMaxDynamicSharedMemorySize, 65536);

    // --- launch order: my launch #4 is the enc_proj GEMM (ncu lands there) ---
    // 1. embed + state init + barrier reset
    k_embed<<<(TT2*NB*HD + 255)/256, 256>>>(tok, emb, state);
    // 2-3. conversions needed by enc_proj
    k_cath<<<TT1*NB, 128>>>(enc,        HD, HD, pench, 1024, 0, 512, 0);   // A2
    k_cath<<<512,    128>>>(wa_W + HD, 2*HD, HD, pWeh, 1024, 0, 512, 1);   // B2
    // 4. enc_proj = enc @ We^T + wa_b   (M=4096, N=512, K'=1024)  << profiled
    k_gemmh<<<dim3(HD/128, (TT1*NB)/128), 256>>>((const uint_t*)pench, 512,
        (const uint_t*)pWeh, 512, wa_b, pep, HD, 1024);
    // 5-6. conversions for q
    k_cath<<<512,    128>>>(wa_W,      2*HD, HD, pWxh, 1024, 0, 512, 1);   // B2
    k_cath<<<TT2*NB, 128>>>(pX,         HD, HD, pXh,  1024, 0, 512, 0);    // A2
    // 7. q = X @ Wx^T                   (M=2048, N=512, K'=1024)
    k_gemmh<<<dim3(HD/128, (TT2*NB)/128), 256>>>((const uint_t*)pXh, 512,
        (const uint_t*)pWxh, 512, nullptr, pq, HD, 1024);

    // remaining conversions
    k_cath<<<H3,     256>>>(W_ih0, 2*HD, 2*HD, pWih0h, 2048, 0, 1024, 1);  // B2
    k_cath<<<VOC,    128>>>(out_W,   HD,   HD, poWh,    512, 0, 0, 2);     // 1-term
    k_cath<<<TT2*NB, 128>>>(pX,      HD,   HD, pXavh,  2048, 0, 1024, 0);  // A2 (X part)

    // attention
    k_att_scores<<<dim3(TT2/8, NB), 256>>>(va_W, dout);
    k_attv<<<dim3(NB, TT2/32, HD/256), 256>>>(enc);
    k_cath<<<TT2*NB, 128>>>(pav, HD, HD, pXavh, 2048, 512, 1536, 0);       // A2 (av part)

    // gi0 = [X, att_v] @ W_ih0^T + b_ih0   (M=2048, N=1536, K'=2048)
    k_gemmh<<<dim3(H3/128, (TT2*NB)/128), 256>>>((const uint_t*)pXavh, 1024,
        (const uint_t*)pWih0h, 1024, b_ih0, pgi0, H3, 2048);

    // recurrence (64KB dynamic smem per block)
    k_rec<<<NBLK, 256, 65536>>>(W_hh0, b_hh0, W_ih1, b_ih1, W_hh1, b_hh1);

    // y = ys @ out_W^T + out_b   (M=2048, N=32000, K=512, 1-term fp16)
    k_cath<<<TT2*NB, 128>>>(pys, HD, HD, pysh, 512, 0, 0, 2);
    k_gemmh<<<dim3(VOC/128, (TT2*NB)/128), 256>>>((const uint_t*)pysh, 256,
        (const uint_t*)poWh, 256, out_b, dout, VOC, 512);

    // final hidden states
    k_fin<<<(2*BHD + 255)/256, 256>>>(dout);
    (void)in_sizes; (void)n_in; (void)out_size;
}

// round 15
// speedup vs baseline: 1.5217x; 1.1497x over previous
#include <cuda_runtime.h>
#include <cuda_fp16.h>
#include <cstddef>
#include <cstdint>

#define HD   512
#define VOC  32000
#define TT1  128
#define TT2  64
#define NB   32
#define H3   1536
#define BHD  (NB*HD)
#define YSZ  ((size_t)TT2*NB*VOC)
#define HF_OFF YSZ
#define LS_OFF (YSZ + (size_t)2*BHD)

typedef unsigned int uint_t;

// ---------------- scratch (device globals; no runtime alloc) ----------------
__device__ float g_X  [TT2*NB*HD];
__device__ float g_q  [TT2*NB*HD];
__device__ float g_ep [TT1*NB*HD];
__device__ float g_sc [TT2*TT1*NB];
__device__ float g_av [TT2*NB*HD];
__device__ float g_gi0[TT2*NB*H3];
__device__ float g_ys [TT2*NB*HD];
__device__ float g_h0c[2*BHD];
__device__ float g_h1c[2*BHD];

// fp16 operands
__device__ __align__(16) __half h_ench [(size_t)TT1*NB * 1024];  // A2: [hi|lo]
__device__ __align__(16) __half h_Wxh  [512 * 1024];             // B2: [hi|hi]
__device__ __align__(16) __half h_Weh  [512 * 1024];             // B2
__device__ __align__(16) __half h_Xh   [(size_t)TT2*NB * 1024];  // A2
__device__ __align__(16) __half h_Xavh [(size_t)TT2*NB * 2048];  // A2 of [X|av]
__device__ __align__(16) __half h_Wih0h[(size_t)H3 * 2048];      // B2
__device__ __align__(16) __half h_oWh  [(size_t)VOC * 512];      // 1-term
__device__ __align__(16) __half h_ysh  [(size_t)TT2*NB * 512];   // 1-term

// grid barrier state (monotonic; reset by k_embed each launch)
__device__ unsigned g_bcnt = 0;

__device__ __forceinline__ int CH(int b, int k){ return ((k>>2)<<7) + (b<<2) + (k&3); }

__device__ __forceinline__ float fast_tanh(float x){
    float e = __expf(2.f*x);
    return 1.f - __fdividef(2.f, e + 1.f);
}
__device__ __forceinline__ float fast_sig(float x){
    return __fdividef(1.f, 1.f + __expf(-x));
}

// ---------------- embed + state init + barrier reset ----------------
__global__ __launch_bounds__(256) void k_embed(const int* __restrict__ tok,
                                               const float* __restrict__ emb,
                                               const float* __restrict__ state)
{
    int i = blockIdx.x*256 + threadIdx.x;
    if (i == 0) g_bcnt = 0;
    if (i < TT2*NB*HD){
        int row = i >> 9;
        int h   = i & (HD-1);
        g_X[i] = emb[(size_t)tok[row]*HD + h];
    }
    if (i < 2*BHD){
        int l = (i >= BHD);
        int r = i & (BHD-1);
        int b = r >> 9, h = r & (HD-1);
        float v = state[i];
        if (l == 0) g_h0c[CH(b,h)] = v;
        else        g_h1c[CH(b,h)] = v;
    }
}

// ---------------- fp32 -> fp16 split conversion ----------------
__device__ __forceinline__ uint_t packh(__half a, __half b){
    return ((uint_t)__half_as_ushort(b) << 16) | (uint_t)__half_as_ushort(a);
}
__global__ void k_cath(const float* __restrict__ src, int src_ld, int Ksrc,
                       __half* __restrict__ dst, int dst_ld,
                       int off0, int off1, int mode)
{
    int row = blockIdx.x;
    for (int k = threadIdx.x*4; k < Ksrc; k += blockDim.x*4){
        float4 v = *reinterpret_cast<const float4*>(src + (size_t)row*src_ld + k);
        __half h0 = __float2half_rn(v.x), h1 = __float2half_rn(v.y);
        __half h2 = __float2half_rn(v.z), h3 = __float2half_rn(v.w);
        uint2 hv = make_uint2(packh(h0,h1), packh(h2,h3));
        *reinterpret_cast<uint2*>(dst + (size_t)row*dst_ld + off0 + k) = hv;
        if (mode == 0){
            __half l0 = __float2half_rn(v.x - __half2float(h0));
            __half l1 = __float2half_rn(v.y - __half2float(h1));
            __half l2 = __float2half_rn(v.z - __half2float(h2));
            __half l3 = __float2half_rn(v.w - __half2float(h3));
            uint2 lv = make_uint2(packh(l0,l1), packh(l2,l3));
            *reinterpret_cast<uint2*>(dst + (size_t)row*dst_ld + off1 + k) = lv;
        } else if (mode == 1){
            *reinterpret_cast<uint2*>(dst + (size_t)row*dst_ld + off1 + k) = hv;
        }
    }
}

// ---------------- fp16 GEMM (R12: cp.async 2-stage, stride-20 smem) ---------
__device__ __forceinline__ uint32_t s2u(const void* p){
    uint32_t a;
    asm("{ .reg .u64 t; cvta.to.shared.u64 t, %1; cvt.u32.u64 %0, t; }" : "=r"(a) : "l"(p));
    return a;
}
__device__ __forceinline__ void cpa16(uint32_t s, const void* g){
    asm volatile("cp.async.cg.shared.global [%0], [%1], 16;" :: "r"(s), "l"(g));
}
__device__ __forceinline__ void mma16f(float* d, const uint_t* a, uint_t b0, uint_t b1){
    asm volatile("mma.sync.aligned.m16n8k16.row.col.f32.f16.f16.f32 "
        "{%0,%1,%2,%3}, {%4,%5,%6,%7}, {%8,%9}, {%0,%1,%2,%3};\n"
        : "+f"(d[0]), "+f"(d[1]), "+f"(d[2]), "+f"(d[3])
        : "r"(a[0]), "r"(a[1]), "r"(a[2]), "r"(a[3]), "r"(b0), "r"(b1));
}
#define SROW 20

__global__ __launch_bounds__(256, 2) void k_gemmh(
    const uint_t* __restrict__ A, int lda,
    const uint_t* __restrict__ B, int ldb,
    const float* __restrict__ bias,
    float* __restrict__ C, int ldc, int K)
{
    __shared__ __align__(16) uint_t sA[2][128*SROW], sB[2][128*SROW];
    const int m0 = blockIdx.y * 128;
    const int n0 = blockIdx.x * 128;
    const int tid = threadIdx.x, lane = tid & 31, warp = tid >> 5;
    const int wm = (warp & 1) * 64;
    const int wn = (warp >> 1) * 32;
    const int g  = lane >> 2, tg = lane & 3;

    const int nch = K >> 5;
    const int lrow = tid >> 1;
    const int lp   = (tid & 1) * 8;

    float acc[4][4][4];
    #pragma unroll
    for (int i=0;i<4;i++)
        #pragma unroll
        for (int j=0;j<4;j++){ acc[i][j][0]=0.f; acc[i][j][1]=0.f; acc[i][j][2]=0.f; acc[i][j][3]=0.f; }

    auto load_stage = [&](int c){
        const int st  = c & 1;
        const int khu = c * 16;
        const uint_t* ga = A + (size_t)(m0 + lrow)*lda + khu + lp;
        const uint_t* gb = B + (size_t)(n0 + lrow)*ldb + khu + lp;
        uint32_t da = s2u(&sA[st][lrow*SROW + lp]);
        uint32_t db = s2u(&sB[st][lrow*SROW + lp]);
        cpa16(da,      ga);
        cpa16(da + 16, ga + 4);
        cpa16(db,      gb);
        cpa16(db + 16, gb + 4);
        asm volatile("cp.async.commit_group;" ::: "memory");
    };

    load_stage(0);
    for (int c = 0; c < nch; c++){
        asm volatile("cp.async.wait_group 0;" ::: "memory");
        __syncthreads();
        if (c + 1 < nch) load_stage(c + 1);
        const int st = c & 1;
        #pragma unroll
        for (int h2=0; h2<2; h2++){
            const int kb2 = h2*8;
            const int P0 = kb2 + tg;
            const int P1 = kb2 + tg + 4;
            #pragma unroll
            for (int mp=0; mp<2; mp++){
                uint_t ah[2][4];
                #pragma unroll
                for (int q=0;q<2;q++){
                    int r0 = wm + (mp*2+q)*16 + g;
                    ah[q][0]=sA[st][r0*SROW + P0];     ah[q][1]=sA[st][(r0+8)*SROW + P0];
                    ah[q][2]=sA[st][r0*SROW + P1];     ah[q][3]=sA[st][(r0+8)*SROW + P1];
                }
                #pragma unroll
                for (int ns=0; ns<4; ns++){
                    int col = wn + ns*8 + g;
                    uint_t b0 = sB[st][col*SROW + P0];
                    uint_t b1 = sB[st][col*SROW + P1];
                    #pragma unroll
                    for (int q=0;q<2;q++)
                        mma16f(acc[mp*2+q][ns], ah[q], b0, b1);
                }
            }
        }
        __syncthreads();
    }
    #pragma unroll
    for (int ms=0; ms<4; ms++){
        #pragma unroll
        for (int ns=0; ns<4; ns++){
            int r0  = m0 + wm + ms*16 + g;
            int col = n0 + wn + ns*8 + tg*2;
            float b0v = 0.f, b1v = 0.f;
            if (bias){ b0v = bias[col]; b1v = bias[col+1]; }
            float2 v0 = make_float2(acc[ms][ns][0]+b0v, acc[ms][ns][1]+b1v);
            float2 v1 = make_float2(acc[ms][ns][2]+b0v, acc[ms][ns][3]+b1v);
            *reinterpret_cast<float2*>(C + (size_t)r0*ldc + col)     = v0;
            *reinterpret_cast<float2*>(C + (size_t)(r0+8)*ldc + col) = v1;
        }
    }
}

// ---------------- attention logits + softmax ----------------
__global__ __launch_bounds__(256) void k_att_scores(const float* __restrict__ va,
                                                    float* __restrict__ dout)
{
    __shared__ float q8[8*HD];
    __shared__ float vsm[HD];
    __shared__ float esm[8*TT1];
    const int b   = blockIdx.y;
    const int t2b = blockIdx.x * 8;
    const int tid = threadIdx.x, lane = tid & 31, w = tid >> 5;

    for (int i = tid; i < 8*HD; i += 256){
        int t2i = i >> 9, h = i & (HD-1);
        q8[i] = g_q[((size_t)(t2b + t2i)*NB + b)*HD + h];
    }
    for (int i = tid; i < HD; i += 256) vsm[i] = va[i];
    __syncthreads();

    for (int t1 = w; t1 < TT1; t1 += 8){
        const float* ep = g_ep + ((size_t)t1*NB + b)*HD;
        float accv[8];
        #pragma unroll
        for (int i=0;i<8;i++) accv[i] = 0.f;
        for (int h = lane; h < HD; h += 32){
            float e  = ep[h];
            float vv = vsm[h];
            #pragma unroll
            for (int i=0;i<8;i++) accv[i] += vv * fast_tanh(q8[i*HD + h] + e);
        }
        #pragma unroll
        for (int i=0;i<8;i++){
            float s = accv[i];
            #pragma unroll
            for (int o=16;o;o>>=1) s += __shfl_xor_sync(0xffffffffu, s, o);
            if (lane == 0) esm[i*TT1 + t1] = s;
        }
    }
    __syncthreads();

    {
        float v[4];
        #pragma unroll
        for (int i=0;i<4;i++) v[i] = esm[w*TT1 + lane + 32*i];
        float m = fmaxf(fmaxf(v[0],v[1]), fmaxf(v[2],v[3]));
        #pragma unroll
        for (int o=16;o;o>>=1) m = fmaxf(m, __shfl_xor_sync(0xffffffffu, m, o));
        float s = 0.f;
        #pragma unroll
        for (int i=0;i<4;i++){ v[i] = __expf(v[i]-m); s += v[i]; }
        #pragma unroll
        for (int o=16;o;o>>=1) s += __shfl_xor_sync(0xffffffffu, s, o);
        float inv = __fdividef(1.f, s);
        int t2 = t2b + w;
        #pragma unroll
        for (int i=0;i<4;i++){
            int t1 = lane + 32*i;
            float sc = v[i]*inv;
            g_sc[((size_t)t2*TT1 + t1)*NB + b] = sc;
            if (t2 == TT2-1) dout[LS_OFF + (size_t)t1*NB + b] = sc;
        }
    }
}

// ---------------- attention values ----------------
__global__ __launch_bounds__(256) void k_attv(const float* __restrict__ enc)
{
    __shared__ float sst[TT1*32];
    const int b   = blockIdx.x;
    const int t2o = blockIdx.y * 32;
    const int h   = blockIdx.z * 256 + threadIdx.x;
    for (int i = threadIdx.x; i < 32*TT1; i += 256){
        int t1 = i >> 5, i2 = i & 31;
        sst[t1*32 + i2] = g_sc[((size_t)(t2o + i2)*TT1 + t1)*NB + b];
    }
    __syncthreads();
    float acc[32];
    #pragma unroll
    for (int i=0;i<32;i++) acc[i] = 0.f;
    for (int t1 = 0; t1 < TT1; t1++){
        float ev = enc[((size_t)t1*NB + b)*HD + h];
        #pragma unroll
        for (int i=0;i<32;i++) acc[i] += ev * sst[t1*32 + i];
    }
    #pragma unroll
    for (int i=0;i<32;i++)
        g_av[((size_t)(t2o+i)*NB + b)*HD + h] = acc[i];
}

// ---------------- persistent recurrence v3: uniform single-wave -------------
// 128 blocks x 384 threads (12 warps), 1 block/SM, single wave, zero skew.
// warp-unit slots s = blk*12 + warp, s in [0,1536):
//   s <  1024 : gru1 unit, pair p = s>>1 (j = p), mat = s&1 (0: W_ih1*h0, 1: W_hh1*h1)
//   s >= 1024 : gru0 unit, j = s - 1024
// smem: sh[0:BHD) = h0[t&1] stage; sh[BHD:2*BHD) = h1[(t-1)&1] stage.
#define NBLK2 128

__device__ __forceinline__ void dotsm(const float* __restrict__ W, int j,
                                      const float* __restrict__ shb, int b,
                                      float& s0, float& s1, float& s2)
{
    const float* w0 = W + (size_t) j        *HD;
    const float* w1 = W + (size_t)(j+ 512)  *HD;
    const float* w2 = W + (size_t)(j+1024)  *HD;
    float a0=0.f, a1=0.f, a2=0.f;
    #pragma unroll 8
    for (int kk = 0; kk < HD; kk += 4){
        float4 hv = *reinterpret_cast<const float4*>(shb + ((kk>>2)<<7) + (b<<2));
        float4 x = *reinterpret_cast<const float4*>(w0 + kk);
        float4 y = *reinterpret_cast<const float4*>(w1 + kk);
        float4 z = *reinterpret_cast<const float4*>(w2 + kk);
        a0 += x.x*hv.x + x.y*hv.y + x.z*hv.z + x.w*hv.w;
        a1 += y.x*hv.x + y.y*hv.y + y.z*hv.z + y.w*hv.w;
        a2 += z.x*hv.x + z.y*hv.y + z.z*hv.z + z.w*hv.w;
    }
    s0 = a0; s1 = a1; s2 = a2;
}

__global__ __launch_bounds__(384, 1) void k_rec(
    const float* __restrict__ W_hh0, const float* __restrict__ b_hh0,
    const float* __restrict__ W_ih1, const float* __restrict__ b_ih1,
    const float* __restrict__ W_hh1, const float* __restrict__ b_hh1)
{
    extern __shared__ float sh[];          // 2*BHD floats = 128 KB
    __shared__ float sm[12][3][32];
    const int blk  = blockIdx.x;
    const int tid  = threadIdx.x;
    const int warp = tid >> 5;
    const int b    = tid & 31;
    const int slot = blk*12 + warp;
    const bool g0u = (slot >= 1024);
    const bool blk_has_g1 = (blk*12 < 1024);

    for (int t = 0; t <= TT2; t++){
        // ---- stage h0[t&1] (+ h1[(t-1)&1] if needed) ----
        {
            const float* sp0 = g_h0c + (t&1)*BHD;
            for (int i = tid*4; i < BHD; i += 1536)
                *reinterpret_cast<float4*>(sh + i) =
                    __ldcg(reinterpret_cast<const float4*>(sp0 + i));
            if (blk_has_g1 && t >= 1){
                const float* sp1 = g_h1c + ((t-1)&1)*BHD;
                for (int i = tid*4; i < BHD; i += 1536)
                    *reinterpret_cast<float4*>(sh + BHD + i) =
                        __ldcg(reinterpret_cast<const float4*>(sp1 + i));
            }
        }
        __syncthreads();

        float s0=0.f, s1=0.f, s2=0.f;
        int j = 0, mat = 0;
        bool act = false;
        if (g0u){
            if (t < TT2){
                act = true;  j = slot - 1024;
                dotsm(W_hh0, j, sh, b, s0, s1, s2);
            }
        } else {
            if (t >= 1){
                act = true;  j = slot >> 1;  mat = slot & 1;
                dotsm(mat ? W_hh1 : W_ih1, j, sh + mat*BHD, b, s0, s1, s2);
            }
        }
        if (!g0u){ sm[warp][0][b] = s0; sm[warp][1][b] = s1; sm[warp][2][b] = s2; }
        __syncthreads();

        if (act){
            if (g0u){
                const float* gi = g_gi0 + ((size_t)t*NB + b)*H3;
                float r = fast_sig (gi[j      ] + s0 + b_hh0[j      ]);
                float z = fast_sig (gi[j+ 512] + s1 + b_hh0[j+ 512]);
                float n = fast_tanh(gi[j+1024] + r*(s2 + b_hh0[j+1024]));
                float hold = sh[CH(b,j)];
                __stcg(&g_h0c[(1-(t&1))*BHD + CH(b,j)], (1.f-z)*n + z*hold);
            } else if (mat == 0){
                const int s = t - 1;
                float xr = s0 + b_ih1[j      ];
                float xz = s1 + b_ih1[j+ 512];
                float xn = s2 + b_ih1[j+1024];
                float hr = sm[warp+1][0][b] + b_hh1[j      ];
                float hz = sm[warp+1][1][b] + b_hh1[j+ 512];
                float hn = sm[warp+1][2][b] + b_hh1[j+1024];
                float r = fast_sig(xr + hr);
                float z = fast_sig(xz + hz);
                float n = fast_tanh(xn + r*hn);
                float h1old = sh[BHD + CH(b,j)];
                float hnew = (1.f-z)*n + z*h1old;
                __stcg(&g_h1c[(t&1)*BHD + CH(b,j)], hnew);
                g_ys[((size_t)s*NB + b)*HD + j] = hnew;
            }
        }
        if (t == TT2) break;
        // ---- grid barrier: release-add + acquire-poll (no L1 flush) ----
        __syncthreads();
        if (tid == 0){
            unsigned old, cur;
            asm volatile("atom.release.gpu.global.add.u32 %0, [%1], %2;"
                         : "=r"(old) : "l"(&g_bcnt), "r"(1u) : "memory");
            const unsigned tgt = (unsigned)(t + 1) * NBLK2;
            do {
                asm volatile("ld.acquire.gpu.global.u32 %0, [%1];"
                             : "=r"(cur) : "l"(&g_bcnt) : "memory");
                if (cur < tgt) __nanosleep(32);
            } while (cur < tgt);
        }
        __syncthreads();
    }
}

// ---------------- final state copy ----------------
__global__ __launch_bounds__(256) void k_fin(float* __restrict__ dout)
{
    int i = blockIdx.x*256 + threadIdx.x;
    if (i >= 2*BHD) return;
    int l = (i >= BHD);
    int r = i & (BHD-1);
    int b = r >> 9, h = r & (HD-1);
    float v = l ? g_h1c[CH(b,h)] : g_h0c[CH(b,h)];
    dout[HF_OFF + i] = v;
}

extern "C" void kernel_launch(void* const* d_in, const int* in_sizes, int n_in,
                              void* d_out, int out_size)
{
    const int*   tok   = (const int*)  d_in[0];
    const float* state = (const float*)d_in[1];
    const float* enc   = (const float*)d_in[2];
    const float* emb   = (const float*)d_in[3];
    const float* wa_W  = (const float*)d_in[4];
    const float* wa_b  = (const float*)d_in[5];
    const float* va_W  = (const float*)d_in[6];
    const float* W_ih0 = (const float*)d_in[7];
    const float* W_hh0 = (const float*)d_in[8];
    const float* b_ih0 = (const float*)d_in[9];
    const float* b_hh0 = (const float*)d_in[10];
    const float* W_ih1 = (const float*)d_in[11];
    const float* W_hh1 = (const float*)d_in[12];
    const float* b_ih1 = (const float*)d_in[13];
    const float* b_hh1 = (const float*)d_in[14];
    const float* out_W = (const float*)d_in[15];
    const float* out_b = (const float*)d_in[16];
    float* dout = (float*)d_out;

    float *pX, *pep, *pq, *pav, *pgi0, *pys;
    __half *pench, *pWxh, *pWeh, *pXh, *pXavh, *pWih0h, *poWh, *pysh;
    cudaGetSymbolAddress((void**)&pX,     g_X);
    cudaGetSymbolAddress((void**)&pep,    g_ep);
    cudaGetSymbolAddress((void**)&pq,     g_q);
    cudaGetSymbolAddress((void**)&pav,    g_av);
    cudaGetSymbolAddress((void**)&pgi0,   g_gi0);
    cudaGetSymbolAddress((void**)&pys,    g_ys);
    cudaGetSymbolAddress((void**)&pench,  h_ench);
    cudaGetSymbolAddress((void**)&pWxh,   h_Wxh);
    cudaGetSymbolAddress((void**)&pWeh,   h_Weh);
    cudaGetSymbolAddress((void**)&pXh,    h_Xh);
    cudaGetSymbolAddress((void**)&pXavh,  h_Xavh);
    cudaGetSymbolAddress((void**)&pWih0h, h_Wih0h);
    cudaGetSymbolAddress((void**)&poWh,   h_oWh);
    cudaGetSymbolAddress((void**)&pysh,   h_ysh);

    cudaFuncSetAttribute(k_rec, cudaFuncAttributeMaxDynamicSharedMemorySize, 2*BHD*4);

    // --- launch order: my launch #4 is the enc_proj GEMM (ncu lands there) ---
    // 1. embed + state init + barrier reset
    k_embed<<<(TT2*NB*HD + 255)/256, 256>>>(tok, emb, state);
    // 2-3. conversions needed by enc_proj
    k_cath<<<TT1*NB, 128>>>(enc,        HD, HD, pench, 1024, 0, 512, 0);   // A2
    k_cath<<<512,    128>>>(wa_W + HD, 2*HD, HD, pWeh, 1024, 0, 512, 1);   // B2
    // 4. enc_proj = enc @ We^T + wa_b   (M=4096, N=512, K'=1024)  << profiled
    k_gemmh<<<dim3(HD/128, (TT1*NB)/128), 256>>>((const uint_t*)pench, 512,
        (const uint_t*)pWeh, 512, wa_b, pep, HD, 1024);
    // 5-6. conversions for q
    k_cath<<<512,    128>>>(wa_W,      2*HD, HD, pWxh, 1024, 0, 512, 1);   // B2
    k_cath<<<TT2*NB, 128>>>(pX,         HD, HD, pXh,  1024, 0, 512, 0);    // A2
    // 7. q = X @ Wx^T                   (M=2048, N=512, K'=1024)
    k_gemmh<<<dim3(HD/128, (TT2*NB)/128), 256>>>((const uint_t*)pXh, 512,
        (const uint_t*)pWxh, 512, nullptr, pq, HD, 1024);

    // remaining conversions
    k_cath<<<H3,     256>>>(W_ih0, 2*HD, 2*HD, pWih0h, 2048, 0, 1024, 1);  // B2
    k_cath<<<VOC,    128>>>(out_W,   HD,   HD, poWh,    512, 0, 0, 2);     // 1-term
    k_cath<<<TT2*NB, 128>>>(pX,      HD,   HD, pXavh,  2048, 0, 1024, 0);  // A2 (X part)

    // attention
    k_att_scores<<<dim3(TT2/8, NB), 256>>>(va_W, dout);
    k_attv<<<dim3(NB, TT2/32, HD/256), 256>>>(enc);
    k_cath<<<TT2*NB, 128>>>(pav, HD, HD, pXavh, 2048, 512, 1536, 0);       // A2 (av part)

    // gi0 = [X, att_v] @ W_ih0^T + b_ih0   (M=2048, N=1536, K'=2048)
    k_gemmh<<<dim3(H3/128, (TT2*NB)/128), 256>>>((const uint_t*)pXavh, 1024,
        (const uint_t*)pWih0h, 1024, b_ih0, pgi0, H3, 2048);

    // recurrence: 128 blocks x 384 threads, 128 KB dynamic smem, single wave
    k_rec<<<NBLK2, 384, 2*BHD*4>>>(W_hh0, b_hh0, W_ih1, b_ih1, W_hh1, b_hh1);

    // y = ys @ out_W^T + out_b   (M=2048, N=32000, K=512, 1-term fp16)
    k_cath<<<TT2*NB, 128>>>(pys, HD, HD, pysh, 512, 0, 0, 2);
    k_gemmh<<<dim3(VOC/128, (TT2*NB)/128), 256>>>((const uint_t*)pysh, 256,
        (const uint_t*)poWh, 256, out_b, dout, VOC, 512);

    // final hidden states
    k_fin<<<(2*BHD + 255)/256, 256>>>(dout);
    (void)in_sizes; (void)n_in; (void)out_size;
}